// round 2
// baseline (speedup 1.0000x reference)
#include <cuda_runtime.h>
#include <cstdint>

#define BB 2
#define HH 48
#define WW 48
#define CC 96
#define LL (HH*WW)        // 2304
#define DI 192
#define NS 32
#define RR 6
#define KK 4

// ---- scratch (device globals; no allocations allowed) ----
__device__ float  g_xraw [BB*DI*LL];          // pre-conv x half, (b,d,l)
__device__ float  g_xconv[BB*DI*LL];          // conv+silu,      (b,d,l)
__device__ float  g_z    [BB*LL*DI];          // silu(z),        (b,l,d)
__device__ float  g_dts  [BB*KK*LL*RR];       // (b,k,l,r)
__device__ float  g_BC   [BB*KK*LL*2*NS];     // (b,k,l,[B0,C0,B1,C1,...])
__device__ float2 g_du   [BB*KK*DI*LL];       // (delta, u) per (b,k,d,l)
__device__ float  g_y    [(size_t)BB*KK*LL*DI]; // scan out, (b,k,l,d)

__device__ __forceinline__ int scan_map(int k, int l) {
    if (k == 0) return l;
    if (k == 2) return LL - 1 - l;
    int l2 = (k == 1) ? l : (LL - 1 - l);
    int w = l2 / HH, h = l2 % HH;      // wh-order: l = w*H + h
    return h * WW + w;
}

// ================= K1: in_proj + split + silu(z) =================
// grid (B*L/32, 8), block 256. warp computes 6 consecutive e outputs for 32 l's.
__global__ void __launch_bounds__(256) k1_inproj(const float* __restrict__ x,
                                                 const float* __restrict__ ipw) {
    __shared__ float sm[32][97];
    int bl = blockIdx.x;
    int lt = bl % (LL/32), b = bl / (LL/32);
    int l0 = lt * 32;
    int tid = threadIdx.x, lane = tid & 31, wid = tid >> 5;
    for (int i = tid; i < 32*96; i += 256) {
        int j = i / 96, c = i % 96;
        sm[j][c] = x[((size_t)b*LL + l0 + j)*CC + c];
    }
    __syncthreads();
    int e0 = (blockIdx.y * 8 + wid) * 6;   // 0..378
    float acc[6] = {0.f,0.f,0.f,0.f,0.f,0.f};
    #pragma unroll 4
    for (int c4 = 0; c4 < 24; c4++) {
        float s0 = sm[lane][c4*4+0], s1 = sm[lane][c4*4+1];
        float s2 = sm[lane][c4*4+2], s3 = sm[lane][c4*4+3];
        #pragma unroll
        for (int i = 0; i < 6; i++) {
            const float4 wv = *(const float4*)(ipw + (size_t)(e0+i)*CC + c4*4);
            acc[i] = fmaf(wv.x, s0, acc[i]);
            acc[i] = fmaf(wv.y, s1, acc[i]);
            acc[i] = fmaf(wv.z, s2, acc[i]);
            acc[i] = fmaf(wv.w, s3, acc[i]);
        }
    }
    int l = l0 + lane;
    #pragma unroll
    for (int i = 0; i < 6; i++) {
        int e = e0 + i;
        if (e < DI) {
            g_xraw[((size_t)b*DI + e)*LL + l] = acc[i];
        } else {
            float v = acc[i];
            g_z[((size_t)b*LL + l)*DI + (e - DI)] = v / (1.f + __expf(-v));
        }
    }
}

// ================= K2: depthwise conv 3x3 + bias + silu =================
__global__ void __launch_bounds__(256) k2_conv(const float* __restrict__ cw,
                                               const float* __restrict__ cb) {
    int idx = blockIdx.x * 256 + threadIdx.x;
    if (idx >= BB*DI*LL) return;
    int l = idx % LL;
    int d = (idx / LL) % DI;
    int b = idx / (DI*LL);
    int h = l / WW, w = l % WW;
    const float* src = g_xraw + ((size_t)b*DI + d)*LL;
    float acc = cb[d];
    #pragma unroll
    for (int dh = -1; dh <= 1; dh++) {
        #pragma unroll
        for (int dw = -1; dw <= 1; dw++) {
            int hh = h + dh, ww2 = w + dw;
            if (hh >= 0 && hh < HH && ww2 >= 0 && ww2 < WW)
                acc = fmaf(src[hh*WW + ww2], cw[d*9 + (dh+1)*3 + (dw+1)], acc);
        }
    }
    g_xconv[idx] = acc / (1.f + __expf(-acc));
}

// ================= K3: x_proj -> dts / interleaved (B,C) =================
// grid B*K*(L/32), block 256. Warp `wid` handles c = wid + 8*i, i<9 (c<70).
__global__ void __launch_bounds__(256) k3_xproj(const float* __restrict__ xpw) {
    __shared__ float sm[96][32];
    int blk = blockIdx.x;
    int lt = blk % (LL/32);
    int bk = blk / (LL/32);
    int k = bk % KK, b = bk / KK;
    int l0 = lt * 32;
    int tid = threadIdx.x, lane = tid & 31, wid = tid >> 5;
    float acc[9];
    #pragma unroll
    for (int i = 0; i < 9; i++) acc[i] = 0.f;

    for (int pass = 0; pass < 2; pass++) {
        for (int i = tid; i < 96*32; i += 256) {
            int dd = i >> 5, j = i & 31;
            sm[dd][j] = g_xconv[((size_t)b*DI + pass*96 + dd)*LL + scan_map(k, l0 + j)];
        }
        __syncthreads();
        #pragma unroll 2
        for (int dd4 = 0; dd4 < 24; dd4++) {
            float s0 = sm[dd4*4+0][lane], s1 = sm[dd4*4+1][lane];
            float s2 = sm[dd4*4+2][lane], s3 = sm[dd4*4+3][lane];
            #pragma unroll
            for (int i = 0; i < 9; i++) {
                int c = wid + 8*i;
                if (c < 70) {
                    const float4 wv = *(const float4*)(xpw + ((size_t)(k*70 + c))*DI + pass*96 + dd4*4);
                    acc[i] = fmaf(wv.x, s0, acc[i]);
                    acc[i] = fmaf(wv.y, s1, acc[i]);
                    acc[i] = fmaf(wv.z, s2, acc[i]);
                    acc[i] = fmaf(wv.w, s3, acc[i]);
                }
            }
        }
        __syncthreads();
    }
    int l = l0 + lane;
    size_t base = (size_t)(b*KK + k)*LL + l;
    #pragma unroll
    for (int i = 0; i < 9; i++) {
        int c = wid + 8*i;
        if (c < 70) {
            float v = acc[i];
            if (c < 6)       g_dts[base*RR + c] = v;
            else if (c < 38) g_BC[base*64 + 2*(c-6)]      = v;
            else             g_BC[base*64 + 2*(c-38) + 1] = v;
        }
    }
}

// ================= K4: dt_proj + softplus, pack (delta,u) =================
__global__ void __launch_bounds__(256) k4_delta(const float* __restrict__ dtw,
                                                const float* __restrict__ dtb) {
    int idx = blockIdx.x * 256 + threadIdx.x;  // ((b*K+k)*D+d)*L + l
    if (idx >= BB*KK*DI*LL) return;
    int l = idx % LL;
    int d = (idx / LL) % DI;
    int k = (idx / (LL*DI)) % KK;
    int b =  idx / (LL*DI*KK);
    const float* dts = g_dts + ((size_t)(b*KK + k)*LL + l)*RR;
    const float* wr  = dtw + (size_t)(k*DI + d)*RR;
    float xv = dtb[k*DI + d];
    #pragma unroll
    for (int r = 0; r < RR; r++) xv = fmaf(dts[r], wr[r], xv);
    float delta = (xv > 15.f) ? xv : __logf(1.f + __expf(xv));
    float u = g_xconv[((size_t)b*DI + d)*LL + scan_map(k, l)];
    g_du[idx] = make_float2(delta, u);
}

// ================= K5: selective scan (warp per (b,k,d) chain) =================
__global__ void __launch_bounds__(32) k5_scan(const float* __restrict__ alog,
                                              const float* __restrict__ dsv) {
    int wid = blockIdx.x;                 // = (b*K+k)*D + d
    int lane = threadIdx.x;
    int d = wid % DI;
    int k = (wid / DI) % KK;
    int b =  wid / (DI*KK);
    float a   = -__expf(alog[(size_t)(k*DI + d)*NS + lane]);
    float dkd = dsv[k*DI + d];
    const float2* du = g_du + (size_t)wid * LL;
    const float2* bc = ((const float2*)g_BC) + ((size_t)(b*KK + k)*LL)*NS + lane;
    float* yo = g_y + ((size_t)(b*KK + k)*LL)*DI + d;
    float h = 0.f;
    #pragma unroll 4
    for (int l = 0; l < LL; l++) {
        float2 dv = du[l];                     // broadcast (delta, u)
        float2 bv = bc[(size_t)l * NS];        // lane's (B_n, C_n)
        float wexp = __expf(dv.x * a);
        float x = dv.x * dv.y;                 // delta*u
        h = fmaf(h, wexp, x * bv.x);
        float p = h * bv.y;
        p += __shfl_xor_sync(0xffffffffu, p, 16);
        p += __shfl_xor_sync(0xffffffffu, p, 8);
        p += __shfl_xor_sync(0xffffffffu, p, 4);
        p += __shfl_xor_sync(0xffffffffu, p, 2);
        p += __shfl_xor_sync(0xffffffffu, p, 1);
        if (lane == 0) yo[(size_t)l * DI] = fmaf(dkd, dv.y, p);
    }
}

// ================= K6: combine dirs + LN + gate + out_proj + residual =====
__global__ void __launch_bounds__(192) k6_out(const float* __restrict__ x,
                                              const float* __restrict__ lnw,
                                              const float* __restrict__ lnb,
                                              const float* __restrict__ opw,
                                              float* __restrict__ out) {
    __shared__ float sy[DI];
    __shared__ float part[DI];
    __shared__ float rs[6], rq[6];
    int b = blockIdx.x / LL, p = blockIdx.x % LL;
    int h = p / WW, w = p % WW;
    int l1 = w * HH + h;
    int d = threadIdx.x;
    size_t base = (size_t)b * KK * LL * DI;
    float y = g_y[base + ((size_t)0*LL + p)           *DI + d]
            + g_y[base + ((size_t)2*LL + (LL-1-p))    *DI + d]
            + g_y[base + ((size_t)1*LL + l1)          *DI + d]
            + g_y[base + ((size_t)3*LL + (LL-1-l1))   *DI + d];
    float s1 = y, s2 = y*y;
    #pragma unroll
    for (int o = 16; o; o >>= 1) {
        s1 += __shfl_xor_sync(0xffffffffu, s1, o);
        s2 += __shfl_xor_sync(0xffffffffu, s2, o);
    }
    int lane = d & 31, wd = d >> 5;
    if (lane == 0) { rs[wd] = s1; rq[wd] = s2; }
    __syncthreads();
    float tot = 0.f, totq = 0.f;
    #pragma unroll
    for (int i = 0; i < 6; i++) { tot += rs[i]; totq += rq[i]; }
    float mu  = tot  * (1.f/DI);
    float var = totq * (1.f/DI) - mu*mu;
    float inv = rsqrtf(var + 1e-5f);
    float yn = (y - mu) * inv * lnw[d] + lnb[d];
    yn *= g_z[((size_t)b*LL + p)*DI + d];
    sy[d] = yn;
    __syncthreads();
    int c = d % 96, half = d / 96;
    float acc = 0.f;
    const float4* wr = (const float4*)(opw + (size_t)c*DI + half*96);
    const float4* sp = (const float4*)(sy + half*96);
    #pragma unroll 6
    for (int j = 0; j < 24; j++) {
        float4 wv = wr[j];
        float4 sv = sp[j];
        acc = fmaf(wv.x, sv.x, acc);
        acc = fmaf(wv.y, sv.y, acc);
        acc = fmaf(wv.z, sv.z, acc);
        acc = fmaf(wv.w, sv.w, acc);
    }
    part[d] = acc;
    __syncthreads();
    if (d < 96) {
        size_t o = ((size_t)b*LL + p)*CC + d;
        out[o] = x[o] + part[d] + part[d + 96];
    }
}

extern "C" void kernel_launch(void* const* d_in, const int* in_sizes, int n_in,
                              void* d_out, int out_size) {
    const float* x    = (const float*)d_in[0];
    const float* ipw  = (const float*)d_in[1];
    const float* cw   = (const float*)d_in[2];
    const float* cb   = (const float*)d_in[3];
    const float* xpw  = (const float*)d_in[4];
    const float* dtw  = (const float*)d_in[5];
    const float* dtb  = (const float*)d_in[6];
    const float* alog = (const float*)d_in[7];
    const float* dsv  = (const float*)d_in[8];
    const float* lnw  = (const float*)d_in[9];
    const float* lnb  = (const float*)d_in[10];
    const float* opw  = (const float*)d_in[11];
    float* out = (float*)d_out;

    dim3 g1(BB * (LL/32), 8);
    k1_inproj<<<g1, 256>>>(x, ipw);

    k2_conv<<<(BB*DI*LL + 255)/256, 256>>>(cw, cb);

    k3_xproj<<<BB*KK*(LL/32), 256>>>(xpw);

    k4_delta<<<(BB*KK*DI*LL + 255)/256, 256>>>(dtw, dtb);

    k5_scan<<<BB*KK*DI, 32>>>(alog, dsv);

    k6_out<<<BB*LL, 192>>>(x, lnw, lnb, opw, out);

    (void)in_sizes; (void)n_in; (void)out_size;
}

// round 3
// speedup vs baseline: 2.0653x; 2.0653x over previous
#include <cuda_runtime.h>
#include <cstdint>

#define BB 2
#define HH 48
#define WW 48
#define CC 96
#define LL (HH*WW)        // 2304
#define DI 192
#define NS 32
#define RR 6
#define KK 4

// ---- scratch (device globals; no allocations allowed) ----
__device__ float  g_xraw [BB*DI*LL];          // pre-conv x half, (b,d,l)
__device__ float  g_xconv[BB*DI*LL];          // conv+silu,      (b,d,l)
__device__ float  g_z    [BB*LL*DI];          // silu(z),        (b,l,d)
__device__ float  g_dts  [BB*KK*LL*RR];       // (b,k,l,r)
__device__ float  g_BC   [BB*KK*LL*2*NS];     // (b,k,l,[B0,C0,B1,C1,...])
__device__ float2 g_du   [BB*KK*DI*LL];       // (delta, u) per (b,k,d,l)
__device__ float  g_y    [(size_t)BB*KK*LL*DI]; // scan out, (b,k,l,d)

__device__ __forceinline__ int scan_map(int k, int l) {
    if (k == 0) return l;
    if (k == 2) return LL - 1 - l;
    int l2 = (k == 1) ? l : (LL - 1 - l);
    int w = l2 / HH, h = l2 % HH;      // wh-order: l = w*H + h
    return h * WW + w;
}

// ================= K1: in_proj + split + silu(z) =================
__global__ void __launch_bounds__(256) k1_inproj(const float* __restrict__ x,
                                                 const float* __restrict__ ipw) {
    __shared__ float sm[32][97];
    int bl = blockIdx.x;
    int lt = bl % (LL/32), b = bl / (LL/32);
    int l0 = lt * 32;
    int tid = threadIdx.x, lane = tid & 31, wid = tid >> 5;
    for (int i = tid; i < 32*96; i += 256) {
        int j = i / 96, c = i % 96;
        sm[j][c] = x[((size_t)b*LL + l0 + j)*CC + c];
    }
    __syncthreads();
    int e0 = (blockIdx.y * 8 + wid) * 6;   // 0..378
    float acc[6] = {0.f,0.f,0.f,0.f,0.f,0.f};
    #pragma unroll 4
    for (int c4 = 0; c4 < 24; c4++) {
        float s0 = sm[lane][c4*4+0], s1 = sm[lane][c4*4+1];
        float s2 = sm[lane][c4*4+2], s3 = sm[lane][c4*4+3];
        #pragma unroll
        for (int i = 0; i < 6; i++) {
            const float4 wv = *(const float4*)(ipw + (size_t)(e0+i)*CC + c4*4);
            acc[i] = fmaf(wv.x, s0, acc[i]);
            acc[i] = fmaf(wv.y, s1, acc[i]);
            acc[i] = fmaf(wv.z, s2, acc[i]);
            acc[i] = fmaf(wv.w, s3, acc[i]);
        }
    }
    int l = l0 + lane;
    #pragma unroll
    for (int i = 0; i < 6; i++) {
        int e = e0 + i;
        if (e < DI) {
            g_xraw[((size_t)b*DI + e)*LL + l] = acc[i];
        } else {
            float v = acc[i];
            g_z[((size_t)b*LL + l)*DI + (e - DI)] = v / (1.f + __expf(-v));
        }
    }
}

// ================= K2: depthwise conv 3x3 + bias + silu =================
__global__ void __launch_bounds__(256) k2_conv(const float* __restrict__ cw,
                                               const float* __restrict__ cb) {
    int idx = blockIdx.x * 256 + threadIdx.x;
    if (idx >= BB*DI*LL) return;
    int l = idx % LL;
    int d = (idx / LL) % DI;
    int b = idx / (DI*LL);
    int h = l / WW, w = l % WW;
    const float* src = g_xraw + ((size_t)b*DI + d)*LL;
    float acc = cb[d];
    #pragma unroll
    for (int dh = -1; dh <= 1; dh++) {
        #pragma unroll
        for (int dw = -1; dw <= 1; dw++) {
            int hh = h + dh, ww2 = w + dw;
            if (hh >= 0 && hh < HH && ww2 >= 0 && ww2 < WW)
                acc = fmaf(src[hh*WW + ww2], cw[d*9 + (dh+1)*3 + (dw+1)], acc);
        }
    }
    g_xconv[idx] = acc / (1.f + __expf(-acc));
}

// ================= K3: x_proj -> dts / interleaved (B,C) =================
__global__ void __launch_bounds__(256) k3_xproj(const float* __restrict__ xpw) {
    __shared__ float sm[96][32];
    int blk = blockIdx.x;
    int lt = blk % (LL/32);
    int bk = blk / (LL/32);
    int k = bk % KK, b = bk / KK;
    int l0 = lt * 32;
    int tid = threadIdx.x, lane = tid & 31, wid = tid >> 5;
    float acc[9];
    #pragma unroll
    for (int i = 0; i < 9; i++) acc[i] = 0.f;

    for (int pass = 0; pass < 2; pass++) {
        for (int i = tid; i < 96*32; i += 256) {
            int dd = i >> 5, j = i & 31;
            sm[dd][j] = g_xconv[((size_t)b*DI + pass*96 + dd)*LL + scan_map(k, l0 + j)];
        }
        __syncthreads();
        #pragma unroll 2
        for (int dd4 = 0; dd4 < 24; dd4++) {
            float s0 = sm[dd4*4+0][lane], s1 = sm[dd4*4+1][lane];
            float s2 = sm[dd4*4+2][lane], s3 = sm[dd4*4+3][lane];
            #pragma unroll
            for (int i = 0; i < 9; i++) {
                int c = wid + 8*i;
                if (c < 70) {
                    const float4 wv = *(const float4*)(xpw + ((size_t)(k*70 + c))*DI + pass*96 + dd4*4);
                    acc[i] = fmaf(wv.x, s0, acc[i]);
                    acc[i] = fmaf(wv.y, s1, acc[i]);
                    acc[i] = fmaf(wv.z, s2, acc[i]);
                    acc[i] = fmaf(wv.w, s3, acc[i]);
                }
            }
        }
        __syncthreads();
    }
    int l = l0 + lane;
    size_t base = (size_t)(b*KK + k)*LL + l;
    #pragma unroll
    for (int i = 0; i < 9; i++) {
        int c = wid + 8*i;
        if (c < 70) {
            float v = acc[i];
            if (c < 6)       g_dts[base*RR + c] = v;
            else if (c < 38) g_BC[base*64 + 2*(c-6)]      = v;
            else             g_BC[base*64 + 2*(c-38) + 1] = v;
        }
    }
}

// ================= K4: dt_proj + softplus, pack (delta,u) =================
__global__ void __launch_bounds__(256) k4_delta(const float* __restrict__ dtw,
                                                const float* __restrict__ dtb) {
    int idx = blockIdx.x * 256 + threadIdx.x;  // ((b*K+k)*D+d)*L + l
    if (idx >= BB*KK*DI*LL) return;
    int l = idx % LL;
    int d = (idx / LL) % DI;
    int k = (idx / (LL*DI)) % KK;
    int b =  idx / (LL*DI*KK);
    const float* dts = g_dts + ((size_t)(b*KK + k)*LL + l)*RR;
    const float* wr  = dtw + (size_t)(k*DI + d)*RR;
    float xv = dtb[k*DI + d];
    #pragma unroll
    for (int r = 0; r < RR; r++) xv = fmaf(dts[r], wr[r], xv);
    float delta = (xv > 15.f) ? xv : __logf(1.f + __expf(xv));
    float u = g_xconv[((size_t)b*DI + d)*LL + scan_map(k, l)];
    g_du[idx] = make_float2(delta, u);
}

// ================= K5: selective scan, R=8 batched reductions =================
// warp per (b,k,d) chain; 4 warps per CTA. Per batch of 8 steps:
//   - vectorized loads (MLP high), 8 independent MUFU exps
//   - 8-step serial h FMA chain (cheap)
//   - ONE 5-level butterfly over 8 independent values (shfls pipeline per level)
//   - single predicated STG: lane i stores y_{l0+i}
__global__ void __launch_bounds__(128) k5_scan(const float* __restrict__ alog,
                                               const float* __restrict__ dsv) {
    int wid = blockIdx.x * 4 + (threadIdx.x >> 5);   // chain id = (b*K+k)*D + d
    int lane = threadIdx.x & 31;
    int d = wid % DI;
    int k = (wid / DI) % KK;
    int b =  wid / (DI*KK);
    float a   = -__expf(alog[(size_t)(k*DI + d)*NS + lane]);
    float dkd = dsv[k*DI + d];
    float dk0 = (lane == 0) ? dkd : 0.f;
    const float4* du4 = (const float4*)(g_du + (size_t)wid * LL);
    const float2* bc  = ((const float2*)g_BC) + ((size_t)(b*KK + k)*LL)*NS + lane;
    float* yo = g_y + ((size_t)(b*KK + k)*LL)*DI + d;
    float h = 0.f;

    for (int l0 = 0; l0 < LL; l0 += 8) {
        // ---- loads (independent, batched) ----
        float4 dub[4];
        float2 bv[8];
        #pragma unroll
        for (int i = 0; i < 4; i++) dub[i] = du4[(l0 >> 1) + i];   // (d0,u0,d1,u1)
        #pragma unroll
        for (int i = 0; i < 8; i++) bv[i] = bc[(size_t)(l0 + i) * NS];

        float dl[8], ul[8];
        #pragma unroll
        for (int i = 0; i < 4; i++) {
            dl[2*i]   = dub[i].x; ul[2*i]   = dub[i].y;
            dl[2*i+1] = dub[i].z; ul[2*i+1] = dub[i].w;
        }

        // ---- 8 independent exps ----
        float w[8];
        #pragma unroll
        for (int i = 0; i < 8; i++) w[i] = __expf(dl[i] * a);

        // ---- serial h chain + per-step products ----
        float p[8];
        #pragma unroll
        for (int i = 0; i < 8; i++) {
            h = fmaf(h, w[i], (dl[i] * ul[i]) * bv[i].x);
            p[i] = fmaf(dk0, ul[i], h * bv[i].y);   // fold D*u into lane 0
        }

        // ---- one butterfly, 8 independent values per level ----
        #pragma unroll
        for (int o = 16; o; o >>= 1) {
            #pragma unroll
            for (int i = 0; i < 8; i++)
                p[i] += __shfl_xor_sync(0xffffffffu, p[i], o);
        }

        // ---- lane i stores y_{l0+i} (full sum is on every lane) ----
        float v = p[0];
        #pragma unroll
        for (int i = 1; i < 8; i++) v = (lane == i) ? p[i] : v;
        if (lane < 8) yo[(size_t)(l0 + lane) * DI] = v;
    }
}

// ================= K6: combine dirs + LN + gate + out_proj + residual =====
__global__ void __launch_bounds__(192) k6_out(const float* __restrict__ x,
                                              const float* __restrict__ lnw,
                                              const float* __restrict__ lnb,
                                              const float* __restrict__ opw,
                                              float* __restrict__ out) {
    __shared__ float sy[DI];
    __shared__ float part[DI];
    __shared__ float rs[6], rq[6];
    int b = blockIdx.x / LL, p = blockIdx.x % LL;
    int h = p / WW, w = p % WW;
    int l1 = w * HH + h;
    int d = threadIdx.x;
    size_t base = (size_t)b * KK * LL * DI;
    float y = g_y[base + ((size_t)0*LL + p)           *DI + d]
            + g_y[base + ((size_t)2*LL + (LL-1-p))    *DI + d]
            + g_y[base + ((size_t)1*LL + l1)          *DI + d]
            + g_y[base + ((size_t)3*LL + (LL-1-l1))   *DI + d];
    float s1 = y, s2 = y*y;
    #pragma unroll
    for (int o = 16; o; o >>= 1) {
        s1 += __shfl_xor_sync(0xffffffffu, s1, o);
        s2 += __shfl_xor_sync(0xffffffffu, s2, o);
    }
    int lane = d & 31, wd = d >> 5;
    if (lane == 0) { rs[wd] = s1; rq[wd] = s2; }
    __syncthreads();
    float tot = 0.f, totq = 0.f;
    #pragma unroll
    for (int i = 0; i < 6; i++) { tot += rs[i]; totq += rq[i]; }
    float mu  = tot  * (1.f/DI);
    float var = totq * (1.f/DI) - mu*mu;
    float inv = rsqrtf(var + 1e-5f);
    float yn = (y - mu) * inv * lnw[d] + lnb[d];
    yn *= g_z[((size_t)b*LL + p)*DI + d];
    sy[d] = yn;
    __syncthreads();
    int c = d % 96, half = d / 96;
    float acc = 0.f;
    const float4* wr = (const float4*)(opw + (size_t)c*DI + half*96);
    const float4* sp = (const float4*)(sy + half*96);
    #pragma unroll 6
    for (int j = 0; j < 24; j++) {
        float4 wv = wr[j];
        float4 sv = sp[j];
        acc = fmaf(wv.x, sv.x, acc);
        acc = fmaf(wv.y, sv.y, acc);
        acc = fmaf(wv.z, sv.z, acc);
        acc = fmaf(wv.w, sv.w, acc);
    }
    part[d] = acc;
    __syncthreads();
    if (d < 96) {
        size_t o = ((size_t)b*LL + p)*CC + d;
        out[o] = x[o] + part[d] + part[d + 96];
    }
}

extern "C" void kernel_launch(void* const* d_in, const int* in_sizes, int n_in,
                              void* d_out, int out_size) {
    const float* x    = (const float*)d_in[0];
    const float* ipw  = (const float*)d_in[1];
    const float* cw   = (const float*)d_in[2];
    const float* cb   = (const float*)d_in[3];
    const float* xpw  = (const float*)d_in[4];
    const float* dtw  = (const float*)d_in[5];
    const float* dtb  = (const float*)d_in[6];
    const float* alog = (const float*)d_in[7];
    const float* dsv  = (const float*)d_in[8];
    const float* lnw  = (const float*)d_in[9];
    const float* lnb  = (const float*)d_in[10];
    const float* opw  = (const float*)d_in[11];
    float* out = (float*)d_out;

    dim3 g1(BB * (LL/32), 8);
    k1_inproj<<<g1, 256>>>(x, ipw);

    k2_conv<<<(BB*DI*LL + 255)/256, 256>>>(cw, cb);

    k3_xproj<<<BB*KK*(LL/32), 256>>>(xpw);

    k4_delta<<<(BB*KK*DI*LL + 255)/256, 256>>>(dtw, dtb);

    k5_scan<<<BB*KK*DI/4, 128>>>(alog, dsv);

    k6_out<<<BB*LL, 192>>>(x, lnw, lnb, opw, out);

    (void)in_sizes; (void)n_in; (void)out_size;
}

// round 7
// speedup vs baseline: 2.4072x; 1.1655x over previous
#include <cuda_runtime.h>
#include <cstdint>

#define BB 2
#define HH 48
#define WW 48
#define CC 96
#define LL (HH*WW)        // 2304
#define DI 192
#define NS 32
#define RR 6
#define KK 4

// ---- scratch (device globals; no allocations allowed) ----
__device__ float  g_xraw [BB*DI*LL];          // pre-conv x half, (b,d,l)
__device__ float  g_xconv[BB*DI*LL];          // conv+silu,      (b,d,l)
__device__ float  g_z    [BB*LL*DI];          // silu(z),        (b,l,d)
__device__ float  g_dts  [BB*KK*RR*LL];       // (b,k,r,l)  r-major for coalesced k4
__device__ float  g_BC   [BB*KK*LL*2*NS];     // (b,k,l,[B0,C0,B1,C1,...])
__device__ float2 g_du   [BB*KK*DI*LL];       // (delta, u) per (b,k,d,l)
__device__ float  g_y    [(size_t)BB*KK*LL*DI]; // scan out, (b,k,l,d)

__device__ __forceinline__ int scan_map(int k, int l) {
    if (k == 0) return l;
    if (k == 2) return LL - 1 - l;
    int l2 = (k == 1) ? l : (LL - 1 - l);
    int w = l2 / HH, h = l2 % HH;      // wh-order: l = w*H + h
    return h * WW + w;
}

// ================= K1: in_proj + split + silu(z) =================
__global__ void __launch_bounds__(256) k1_inproj(const float* __restrict__ x,
                                                 const float* __restrict__ ipw) {
    __shared__ float sm[32][97];
    int bl = blockIdx.x;
    int lt = bl % (LL/32), b = bl / (LL/32);
    int l0 = lt * 32;
    int tid = threadIdx.x, lane = tid & 31, wid = tid >> 5;
    for (int i = tid; i < 32*96; i += 256) {
        int j = i / 96, c = i % 96;
        sm[j][c] = x[((size_t)b*LL + l0 + j)*CC + c];
    }
    __syncthreads();
    int e0 = (blockIdx.y * 8 + wid) * 6;   // 0..378
    float acc[6] = {0.f,0.f,0.f,0.f,0.f,0.f};
    #pragma unroll 4
    for (int c4 = 0; c4 < 24; c4++) {
        float s0 = sm[lane][c4*4+0], s1 = sm[lane][c4*4+1];
        float s2 = sm[lane][c4*4+2], s3 = sm[lane][c4*4+3];
        #pragma unroll
        for (int i = 0; i < 6; i++) {
            const float4 wv = *(const float4*)(ipw + (size_t)(e0+i)*CC + c4*4);
            acc[i] = fmaf(wv.x, s0, acc[i]);
            acc[i] = fmaf(wv.y, s1, acc[i]);
            acc[i] = fmaf(wv.z, s2, acc[i]);
            acc[i] = fmaf(wv.w, s3, acc[i]);
        }
    }
    int l = l0 + lane;
    #pragma unroll
    for (int i = 0; i < 6; i++) {
        int e = e0 + i;
        if (e < DI) {
            g_xraw[((size_t)b*DI + e)*LL + l] = acc[i];
        } else {
            float v = acc[i];
            g_z[((size_t)b*LL + l)*DI + (e - DI)] = v / (1.f + __expf(-v));
        }
    }
}

// ================= K2: depthwise conv 3x3 + bias + silu =================
__global__ void __launch_bounds__(256) k2_conv(const float* __restrict__ cw,
                                               const float* __restrict__ cb) {
    int idx = blockIdx.x * 256 + threadIdx.x;
    if (idx >= BB*DI*LL) return;
    int l = idx % LL;
    int d = (idx / LL) % DI;
    int b = idx / (DI*LL);
    int h = l / WW, w = l % WW;
    const float* src = g_xraw + ((size_t)b*DI + d)*LL;
    float acc = cb[d];
    #pragma unroll
    for (int dh = -1; dh <= 1; dh++) {
        #pragma unroll
        for (int dw = -1; dw <= 1; dw++) {
            int hh = h + dh, ww2 = w + dw;
            if (hh >= 0 && hh < HH && ww2 >= 0 && ww2 < WW)
                acc = fmaf(src[hh*WW + ww2], cw[d*9 + (dh+1)*3 + (dw+1)], acc);
        }
    }
    g_xconv[idx] = acc / (1.f + __expf(-acc));
}

// ================= K3: x_proj -> dts / interleaved (B,C) =================
__global__ void __launch_bounds__(256) k3_xproj(const float* __restrict__ xpw) {
    __shared__ float sm[96][32];
    int blk = blockIdx.x;
    int lt = blk % (LL/32);
    int bk = blk / (LL/32);
    int k = bk % KK, b = bk / KK;
    int l0 = lt * 32;
    int tid = threadIdx.x, lane = tid & 31, wid = tid >> 5;
    float acc[9];
    #pragma unroll
    for (int i = 0; i < 9; i++) acc[i] = 0.f;

    for (int pass = 0; pass < 2; pass++) {
        for (int i = tid; i < 96*32; i += 256) {
            int dd = i >> 5, j = i & 31;
            sm[dd][j] = g_xconv[((size_t)b*DI + pass*96 + dd)*LL + scan_map(k, l0 + j)];
        }
        __syncthreads();
        #pragma unroll 2
        for (int dd4 = 0; dd4 < 24; dd4++) {
            float s0 = sm[dd4*4+0][lane], s1 = sm[dd4*4+1][lane];
            float s2 = sm[dd4*4+2][lane], s3 = sm[dd4*4+3][lane];
            #pragma unroll
            for (int i = 0; i < 9; i++) {
                int c = wid + 8*i;
                if (c < 70) {
                    const float4 wv = *(const float4*)(xpw + ((size_t)(k*70 + c))*DI + pass*96 + dd4*4);
                    acc[i] = fmaf(wv.x, s0, acc[i]);
                    acc[i] = fmaf(wv.y, s1, acc[i]);
                    acc[i] = fmaf(wv.z, s2, acc[i]);
                    acc[i] = fmaf(wv.w, s3, acc[i]);
                }
            }
        }
        __syncthreads();
    }
    int l = l0 + lane;
    size_t basebk = (size_t)(b*KK + k);
    #pragma unroll
    for (int i = 0; i < 9; i++) {
        int c = wid + 8*i;
        if (c < 70) {
            float v = acc[i];
            if (c < 6)       g_dts[(basebk*RR + c)*LL + l] = v;
            else if (c < 38) g_BC[(basebk*LL + l)*64 + 2*(c-6)]      = v;
            else             g_BC[(basebk*LL + l)*64 + 2*(c-38) + 1] = v;
        }
    }
}

// ================= K4: dt_proj + softplus, pack (delta,u) =================
__global__ void __launch_bounds__(256) k4_delta(const float* __restrict__ dtw,
                                                const float* __restrict__ dtb) {
    int idx = blockIdx.x * 256 + threadIdx.x;  // ((b*K+k)*D+d)*L + l
    if (idx >= BB*KK*DI*LL) return;
    int l = idx % LL;
    int d = (idx / LL) % DI;
    int k = (idx / (LL*DI)) % KK;
    int b =  idx / (LL*DI*KK);
    const float* dts = g_dts + (size_t)(b*KK + k)*RR*LL + l;   // coalesced per r
    const float* wr  = dtw + (size_t)(k*DI + d)*RR;            // warp-uniform
    float xv = dtb[k*DI + d];
    #pragma unroll
    for (int r = 0; r < RR; r++) xv = fmaf(dts[(size_t)r*LL], wr[r], xv);
    float delta = (xv > 15.f) ? xv : __logf(1.f + __expf(xv));
    float u = g_xconv[((size_t)b*DI + d)*LL + scan_map(k, l)];
    g_du[idx] = make_float2(delta, u);
}

// ================= K5: selective scan =================
// CTA = 4 warps = 4 d-chains of the same (b,k). B/C staged through smem
// (double-buffered, one float4 LDG+STS per thread per batch). Per batch of 8
// steps: 8 exps, 8-step serial h chain, then a VALUE-HALVING multi-reduction:
// 9 shfls produce all 8 lane-sums (vs 40 for per-output butterflies).
__global__ void __launch_bounds__(128) k5_scan(const float* __restrict__ alog,
                                               const float* __restrict__ dsv) {
    __shared__ float2 sbc[2][8][32];
    int warp = threadIdx.x >> 5;
    int lane = threadIdx.x & 31;
    int tid  = threadIdx.x;
    int wid = blockIdx.x * 4 + warp;      // chain id = (b*K+k)*D + d
    int d = wid % DI;
    int k = (wid / DI) % KK;
    int b =  wid / (DI*KK);
    float a   = -__expf(alog[(size_t)(k*DI + d)*NS + lane]);
    float dk0 = (lane == 0) ? dsv[k*DI + d] : 0.f;
    const float4* du4 = (const float4*)(g_du + (size_t)wid * LL);
    const float4* bc4 = (const float4*)(g_BC + (size_t)(b*KK + k)*LL*64);  // CTA-uniform
    float* yo = g_y + ((size_t)(b*KK + k)*LL)*DI + d;
    float h = 0.f;

    // prologue: stage batch 0 (8 steps * 64 floats = 2KB = 128 float4)
    ((float4*)&sbc[0][0][0])[tid] = bc4[tid];
    __syncthreads();

    #pragma unroll 2
    for (int t = 0; t < LL/8; t++) {
        int cur = t & 1, nxt = cur ^ 1;
        // prefetch next batch's B/C into the other smem buffer
        if (t + 1 < LL/8)
            ((float4*)&sbc[nxt][0][0])[tid] = bc4[(size_t)(t+1)*128 + tid];

        int l0 = t * 8;
        // broadcast (delta,u) loads for 8 steps
        float4 dub[4];
        #pragma unroll
        for (int i = 0; i < 4; i++) dub[i] = du4[(l0 >> 1) + i];  // (d0,u0,d1,u1)

        float dl[8], ul[8], w[8];
        #pragma unroll
        for (int i = 0; i < 4; i++) {
            dl[2*i]   = dub[i].x; ul[2*i]   = dub[i].y;
            dl[2*i+1] = dub[i].z; ul[2*i+1] = dub[i].w;
        }
        #pragma unroll
        for (int i = 0; i < 8; i++) w[i] = __expf(dl[i] * a);

        float p[8];
        #pragma unroll
        for (int i = 0; i < 8; i++) {
            float2 bv = sbc[cur][i][lane];
            h = fmaf(h, w[i], (dl[i] * ul[i]) * bv.x);
            p[i] = fmaf(dk0, ul[i], h * bv.y);
        }

        // ---- value-halving multi-reduction: 9 shfls for 8 sums ----
        {
            bool hi = (lane & 16) != 0;
            #pragma unroll
            for (int i = 0; i < 4; i++) {
                float send = hi ? p[i] : p[i+4];
                float keep = hi ? p[i+4] : p[i];
                p[i] = keep + __shfl_xor_sync(0xffffffffu, send, 16);
            }
        }
        {
            bool hi = (lane & 8) != 0;
            #pragma unroll
            for (int i = 0; i < 2; i++) {
                float send = hi ? p[i] : p[i+2];
                float keep = hi ? p[i+2] : p[i];
                p[i] = keep + __shfl_xor_sync(0xffffffffu, send, 8);
            }
        }
        {
            bool hi = (lane & 4) != 0;
            float send = hi ? p[0] : p[1];
            float keep = hi ? p[1] : p[0];
            p[0] = keep + __shfl_xor_sync(0xffffffffu, send, 4);
        }
        p[0] += __shfl_xor_sync(0xffffffffu, p[0], 2);
        p[0] += __shfl_xor_sync(0xffffffffu, p[0], 1);
        // lane L (L%4==0) holds the full sum for step l0 + (L>>2)
        if ((lane & 3) == 0) yo[(size_t)(l0 + (lane >> 2)) * DI] = p[0];

        __syncthreads();
    }
}

// ================= K6: combine dirs + LN + gate + out_proj + residual =====
__global__ void __launch_bounds__(192) k6_out(const float* __restrict__ x,
                                              const float* __restrict__ lnw,
                                              const float* __restrict__ lnb,
                                              const float* __restrict__ opw,
                                              float* __restrict__ out) {
    __shared__ float sy[DI];
    __shared__ float part[DI];
    __shared__ float rs[6], rq[6];
    int b = blockIdx.x / LL, p = blockIdx.x % LL;
    int h = p / WW, w = p % WW;
    int l1 = w * HH + h;
    int d = threadIdx.x;
    size_t base = (size_t)b * KK * LL * DI;
    float y = g_y[base + ((size_t)0*LL + p)           *DI + d]
            + g_y[base + ((size_t)2*LL + (LL-1-p))    *DI + d]
            + g_y[base + ((size_t)1*LL + l1)          *DI + d]
            + g_y[base + ((size_t)3*LL + (LL-1-l1))   *DI + d];
    float s1 = y, s2 = y*y;
    #pragma unroll
    for (int o = 16; o; o >>= 1) {
        s1 += __shfl_xor_sync(0xffffffffu, s1, o);
        s2 += __shfl_xor_sync(0xffffffffu, s2, o);
    }
    int lane = d & 31, wd = d >> 5;
    if (lane == 0) { rs[wd] = s1; rq[wd] = s2; }
    __syncthreads();
    float tot = 0.f, totq = 0.f;
    #pragma unroll
    for (int i = 0; i < 6; i++) { tot += rs[i]; totq += rq[i]; }
    float mu  = tot  * (1.f/DI);
    float var = totq * (1.f/DI) - mu*mu;
    float inv = rsqrtf(var + 1e-5f);
    float yn = (y - mu) * inv * lnw[d] + lnb[d];
    yn *= g_z[((size_t)b*LL + p)*DI + d];
    sy[d] = yn;
    __syncthreads();
    int c = d % 96, half = d / 96;
    float acc = 0.f;
    const float4* wr = (const float4*)(opw + (size_t)c*DI + half*96);
    const float4* sp = (const float4*)(sy + half*96);
    #pragma unroll 6
    for (int j = 0; j < 24; j++) {
        float4 wv = wr[j];
        float4 sv = sp[j];
        acc = fmaf(wv.x, sv.x, acc);
        acc = fmaf(wv.y, sv.y, acc);
        acc = fmaf(wv.z, sv.z, acc);
        acc = fmaf(wv.w, sv.w, acc);
    }
    part[d] = acc;
    __syncthreads();
    if (d < 96) {
        size_t o = ((size_t)b*LL + p)*CC + d;
        out[o] = x[o] + part[d] + part[d + 96];
    }
}

extern "C" void kernel_launch(void* const* d_in, const int* in_sizes, int n_in,
                              void* d_out, int out_size) {
    const float* x    = (const float*)d_in[0];
    const float* ipw  = (const float*)d_in[1];
    const float* cw   = (const float*)d_in[2];
    const float* cb   = (const float*)d_in[3];
    const float* xpw  = (const float*)d_in[4];
    const float* dtw  = (const float*)d_in[5];
    const float* dtb  = (const float*)d_in[6];
    const float* alog = (const float*)d_in[7];
    const float* dsv  = (const float*)d_in[8];
    const float* lnw  = (const float*)d_in[9];
    const float* lnb  = (const float*)d_in[10];
    const float* opw  = (const float*)d_in[11];
    float* out = (float*)d_out;

    dim3 g1(BB * (LL/32), 8);
    k1_inproj<<<g1, 256>>>(x, ipw);

    k2_conv<<<(BB*DI*LL + 255)/256, 256>>>(cw, cb);

    k3_xproj<<<BB*KK*(LL/32), 256>>>(xpw);

    k4_delta<<<(BB*KK*DI*LL + 255)/256, 256>>>(dtw, dtb);

    k5_scan<<<BB*KK*DI/4, 128>>>(alog, dsv);

    k6_out<<<BB*LL, 192>>>(x, lnw, lnb, opw, out);

    (void)in_sizes; (void)n_in; (void)out_size;
}

// round 8
// speedup vs baseline: 2.7556x; 1.1447x over previous
#include <cuda_runtime.h>
#include <cstdint>

#define BB 2
#define HH 48
#define WW 48
#define CC 96
#define LL (HH*WW)        // 2304
#define DI 192
#define NS 32
#define RR 6
#define KK 4
#define NCH 6
#define CHL (LL/NCH)      // 384

// ---- scratch (device globals; no allocations allowed) ----
__device__ float  g_xraw  [BB*DI*LL];          // pre-conv x half, (b,d,l)
__device__ float  g_xconv [BB*DI*LL];          // conv+silu, hw-order (b,d,l)
__device__ float  g_xconvT[BB*DI*LL];          // conv+silu, wh-order (b,d,j)
__device__ float  g_z     [BB*LL*DI];          // silu(z), (b,l,d)
__device__ float  g_dts   [BB*KK*RR*LL];       // (b,k,r,l)
__device__ float  g_BC    [BB*KK*LL*2*NS];     // (b,k,l,[B0,C0,B1,C1,...])
__device__ float2 g_du    [BB*KK*DI*LL];       // (delta,u) per (b,k,d,l)
__device__ float  g_y     [(size_t)BB*KK*LL*DI]; // scan out, (b,k,l,d)
__device__ float  g_hfin  [BB*KK*DI*NCH*NS];   // chunk-local final states
__device__ float  g_P     [BB*KK*DI*NCH*NS];   // chunk decay products
__device__ float  g_hin   [BB*KK*DI*NCH*NS];   // chunk initial states

// ================= K1: in_proj + split + silu(z) =================
__global__ void __launch_bounds__(256) k1_inproj(const float* __restrict__ x,
                                                 const float* __restrict__ ipw) {
    __shared__ float sm[32][97];
    int bl = blockIdx.x;
    int lt = bl % (LL/32), b = bl / (LL/32);
    int l0 = lt * 32;
    int tid = threadIdx.x, lane = tid & 31, wid = tid >> 5;
    for (int i = tid; i < 32*96; i += 256) {
        int j = i / 96, c = i % 96;
        sm[j][c] = x[((size_t)b*LL + l0 + j)*CC + c];
    }
    __syncthreads();
    int e0 = (blockIdx.y * 8 + wid) * 6;
    float acc[6] = {0.f,0.f,0.f,0.f,0.f,0.f};
    #pragma unroll 4
    for (int c4 = 0; c4 < 24; c4++) {
        float s0 = sm[lane][c4*4+0], s1 = sm[lane][c4*4+1];
        float s2 = sm[lane][c4*4+2], s3 = sm[lane][c4*4+3];
        #pragma unroll
        for (int i = 0; i < 6; i++) {
            const float4 wv = *(const float4*)(ipw + (size_t)(e0+i)*CC + c4*4);
            acc[i] = fmaf(wv.x, s0, acc[i]);
            acc[i] = fmaf(wv.y, s1, acc[i]);
            acc[i] = fmaf(wv.z, s2, acc[i]);
            acc[i] = fmaf(wv.w, s3, acc[i]);
        }
    }
    int l = l0 + lane;
    #pragma unroll
    for (int i = 0; i < 6; i++) {
        int e = e0 + i;
        if (e < DI) {
            g_xraw[((size_t)b*DI + e)*LL + l] = acc[i];
        } else {
            float v = acc[i];
            g_z[((size_t)b*LL + l)*DI + (e - DI)] = v / (1.f + __expf(-v));
        }
    }
}

// ===== K2: depthwise conv 3x3 + bias + silu; writes hw AND wh layouts =====
// One CTA per (b,d) image. Conv from smem; transpose store via padded smem.
__global__ void __launch_bounds__(256) k2_conv(const float* __restrict__ cw,
                                               const float* __restrict__ cb) {
    __shared__ float si[LL];
    __shared__ float so[HH*49];          // padded (stride 49) for transpose
    int bd = blockIdx.x;                 // = b*DI + d
    int d = bd % DI;
    int tid = threadIdx.x;
    const float* src = g_xraw + (size_t)bd * LL;
    for (int i = tid; i < LL; i += 256) si[i] = src[i];
    float wts[9];
    #pragma unroll
    for (int j = 0; j < 9; j++) wts[j] = cw[d*9 + j];
    float bias = cb[d];
    __syncthreads();
    for (int l = tid; l < LL; l += 256) {
        int h = l / WW, w = l % WW;
        float acc = bias;
        #pragma unroll
        for (int dh = -1; dh <= 1; dh++) {
            #pragma unroll
            for (int dw = -1; dw <= 1; dw++) {
                int hh = h + dh, ww2 = w + dw;
                if (hh >= 0 && hh < HH && ww2 >= 0 && ww2 < WW)
                    acc = fmaf(si[hh*WW + ww2], wts[(dh+1)*3 + (dw+1)], acc);
            }
        }
        float v = acc / (1.f + __expf(-acc));
        g_xconv[(size_t)bd*LL + l] = v;
        so[h*49 + w] = v;
    }
    __syncthreads();
    for (int j = tid; j < LL; j += 256) {     // j = w*HH + h
        int w = j / HH, h = j % HH;
        g_xconvT[(size_t)bd*LL + j] = so[h*49 + w];
    }
}

// ================= K3: x_proj -> dts / interleaved (B,C) =================
__global__ void __launch_bounds__(256) k3_xproj(const float* __restrict__ xpw) {
    __shared__ float sm[96][32];
    int blk = blockIdx.x;
    int lt = blk % (LL/32);
    int bk = blk / (LL/32);
    int k = bk % KK, b = bk / KK;
    int l0 = lt * 32;
    int tid = threadIdx.x, lane = tid & 31, wid = tid >> 5;
    const float* xbase = (k & 1) ? g_xconvT : g_xconv;
    float acc[9];
    #pragma unroll
    for (int i = 0; i < 9; i++) acc[i] = 0.f;

    for (int pass = 0; pass < 2; pass++) {
        for (int i = tid; i < 96*32; i += 256) {
            int dd = i >> 5, j = i & 31;
            int l = l0 + j;
            int idx = (k < 2) ? l : (LL - 1 - l);
            sm[dd][j] = xbase[((size_t)b*DI + pass*96 + dd)*LL + idx];
        }
        __syncthreads();
        #pragma unroll 2
        for (int dd4 = 0; dd4 < 24; dd4++) {
            float s0 = sm[dd4*4+0][lane], s1 = sm[dd4*4+1][lane];
            float s2 = sm[dd4*4+2][lane], s3 = sm[dd4*4+3][lane];
            #pragma unroll
            for (int i = 0; i < 9; i++) {
                int c = wid + 8*i;
                if (c < 70) {
                    const float4 wv = *(const float4*)(xpw + ((size_t)(k*70 + c))*DI + pass*96 + dd4*4);
                    acc[i] = fmaf(wv.x, s0, acc[i]);
                    acc[i] = fmaf(wv.y, s1, acc[i]);
                    acc[i] = fmaf(wv.z, s2, acc[i]);
                    acc[i] = fmaf(wv.w, s3, acc[i]);
                }
            }
        }
        __syncthreads();
    }
    int l = l0 + lane;
    size_t basebk = (size_t)(b*KK + k);
    #pragma unroll
    for (int i = 0; i < 9; i++) {
        int c = wid + 8*i;
        if (c < 70) {
            float v = acc[i];
            if (c < 6)       g_dts[(basebk*RR + c)*LL + l] = v;
            else if (c < 38) g_BC[(basebk*LL + l)*64 + 2*(c-6)]      = v;
            else             g_BC[(basebk*LL + l)*64 + 2*(c-38) + 1] = v;
        }
    }
}

// ================= K4: dt_proj + softplus, pack (delta,u) =================
__global__ void __launch_bounds__(256) k4_delta(const float* __restrict__ dtw,
                                                const float* __restrict__ dtb) {
    int idx = blockIdx.x * 256 + threadIdx.x;
    if (idx >= BB*KK*DI*LL) return;
    int l = idx % LL;
    int d = (idx / LL) % DI;
    int k = (idx / (LL*DI)) % KK;
    int b =  idx / (LL*DI*KK);
    const float* dts = g_dts + (size_t)(b*KK + k)*RR*LL + l;
    const float* wr  = dtw + (size_t)(k*DI + d)*RR;
    float xv = dtb[k*DI + d];
    #pragma unroll
    for (int r = 0; r < RR; r++) xv = fmaf(dts[(size_t)r*LL], wr[r], xv);
    float delta = (xv > 15.f) ? xv : __logf(1.f + __expf(xv));
    const float* xbase = (k & 1) ? g_xconvT : g_xconv;
    int midx = (k < 2) ? l : (LL - 1 - l);
    float u = xbase[((size_t)b*DI + d)*LL + midx];
    g_du[idx] = make_float2(delta, u);
}

// ===== K5a: pass 1 — per-chunk local scan: h_fin and decay P =====
// grid (384, NCH), block 128. warp = (b,k,d), chunk = blockIdx.y.
__global__ void __launch_bounds__(128) k5a_pass1(const float* __restrict__ alog) {
    __shared__ float2 sbc[2][8][32];
    int warp = threadIdx.x >> 5;
    int lane = threadIdx.x & 31;
    int tid  = threadIdx.x;
    int wid = blockIdx.x * 4 + warp;
    int ch  = blockIdx.y;
    int d = wid % DI;
    int k = (wid / DI) % KK;
    int b =  wid / (DI*KK);
    float a = -__expf(alog[(size_t)(k*DI + d)*NS + lane]);
    const float4* du4 = (const float4*)(g_du + (size_t)wid * LL);
    const float4* bc4 = (const float4*)(g_BC + (size_t)(b*KK + k)*LL*64)
                        + (size_t)ch * CHL * 16;
    float h = 0.f, S = 0.f;

    ((float4*)&sbc[0][0][0])[tid] = bc4[tid];
    __syncthreads();

    #pragma unroll 2
    for (int t = 0; t < CHL/8; t++) {
        int cur = t & 1, nxt = cur ^ 1;
        if (t + 1 < CHL/8)
            ((float4*)&sbc[nxt][0][0])[tid] = bc4[(size_t)(t+1)*128 + tid];

        int l0 = ch*CHL + t*8;
        float4 dub[4];
        #pragma unroll
        for (int i = 0; i < 4; i++) dub[i] = du4[(l0 >> 1) + i];
        float dl[8], ul[8], w[8];
        #pragma unroll
        for (int i = 0; i < 4; i++) {
            dl[2*i]   = dub[i].x; ul[2*i]   = dub[i].y;
            dl[2*i+1] = dub[i].z; ul[2*i+1] = dub[i].w;
        }
        #pragma unroll
        for (int i = 0; i < 8; i++) w[i] = __expf(dl[i] * a);
        #pragma unroll
        for (int i = 0; i < 8; i++) {
            h = fmaf(h, w[i], (dl[i] * ul[i]) * sbc[cur][i][lane].x);
            S += dl[i];
        }
        __syncthreads();
    }
    size_t o = ((size_t)wid * NCH + ch) * NS + lane;
    g_hfin[o] = h;
    g_P[o]    = __expf(a * S);
}

// ===== K5b: combine chunk states serially (trivial) =====
__global__ void __launch_bounds__(128) k5b_combine() {
    int wid = blockIdx.x * 4 + (threadIdx.x >> 5);
    int lane = threadIdx.x & 31;
    size_t base = (size_t)wid * NCH * NS + lane;
    float hin = 0.f;
    #pragma unroll
    for (int c = 0; c < NCH; c++) {
        g_hin[base + (size_t)c*NS] = hin;
        hin = fmaf(g_P[base + (size_t)c*NS], hin, g_hfin[base + (size_t)c*NS]);
    }
}

// ===== K5c: pass 2 — full scan per chunk from h_in, with y output =====
__global__ void __launch_bounds__(128) k5c_pass2(const float* __restrict__ alog,
                                                 const float* __restrict__ dsv) {
    __shared__ float2 sbc[2][8][32];
    int warp = threadIdx.x >> 5;
    int lane = threadIdx.x & 31;
    int tid  = threadIdx.x;
    int wid = blockIdx.x * 4 + warp;
    int ch  = blockIdx.y;
    int d = wid % DI;
    int k = (wid / DI) % KK;
    int b =  wid / (DI*KK);
    float a = -__expf(alog[(size_t)(k*DI + d)*NS + lane]);
    float dk0 = (lane == 0) ? dsv[k*DI + d] : 0.f;
    const float4* du4 = (const float4*)(g_du + (size_t)wid * LL);
    const float4* bc4 = (const float4*)(g_BC + (size_t)(b*KK + k)*LL*64)
                        + (size_t)ch * CHL * 16;
    float* yo = g_y + ((size_t)(b*KK + k)*LL)*DI + d;
    float h = g_hin[((size_t)wid * NCH + ch) * NS + lane];

    ((float4*)&sbc[0][0][0])[tid] = bc4[tid];
    __syncthreads();

    #pragma unroll 2
    for (int t = 0; t < CHL/8; t++) {
        int cur = t & 1, nxt = cur ^ 1;
        if (t + 1 < CHL/8)
            ((float4*)&sbc[nxt][0][0])[tid] = bc4[(size_t)(t+1)*128 + tid];

        int l0 = ch*CHL + t*8;
        float4 dub[4];
        #pragma unroll
        for (int i = 0; i < 4; i++) dub[i] = du4[(l0 >> 1) + i];
        float dl[8], ul[8], w[8];
        #pragma unroll
        for (int i = 0; i < 4; i++) {
            dl[2*i]   = dub[i].x; ul[2*i]   = dub[i].y;
            dl[2*i+1] = dub[i].z; ul[2*i+1] = dub[i].w;
        }
        #pragma unroll
        for (int i = 0; i < 8; i++) w[i] = __expf(dl[i] * a);

        float p[8];
        #pragma unroll
        for (int i = 0; i < 8; i++) {
            float2 bv = sbc[cur][i][lane];
            h = fmaf(h, w[i], (dl[i] * ul[i]) * bv.x);
            p[i] = fmaf(dk0, ul[i], h * bv.y);
        }

        // value-halving multi-reduction: 9 shfls for 8 sums
        {
            bool hi = (lane & 16) != 0;
            #pragma unroll
            for (int i = 0; i < 4; i++) {
                float send = hi ? p[i] : p[i+4];
                float keep = hi ? p[i+4] : p[i];
                p[i] = keep + __shfl_xor_sync(0xffffffffu, send, 16);
            }
        }
        {
            bool hi = (lane & 8) != 0;
            #pragma unroll
            for (int i = 0; i < 2; i++) {
                float send = hi ? p[i] : p[i+2];
                float keep = hi ? p[i+2] : p[i];
                p[i] = keep + __shfl_xor_sync(0xffffffffu, send, 8);
            }
        }
        {
            bool hi = (lane & 4) != 0;
            float send = hi ? p[0] : p[1];
            float keep = hi ? p[1] : p[0];
            p[0] = keep + __shfl_xor_sync(0xffffffffu, send, 4);
        }
        p[0] += __shfl_xor_sync(0xffffffffu, p[0], 2);
        p[0] += __shfl_xor_sync(0xffffffffu, p[0], 1);
        if ((lane & 3) == 0) yo[(size_t)(l0 + (lane >> 2)) * DI] = p[0];

        __syncthreads();
    }
}

// ================= K6: combine dirs + LN + gate + out_proj + residual =====
__global__ void __launch_bounds__(192) k6_out(const float* __restrict__ x,
                                              const float* __restrict__ lnw,
                                              const float* __restrict__ lnb,
                                              const float* __restrict__ opw,
                                              float* __restrict__ out) {
    __shared__ float sy[DI];
    __shared__ float part[DI];
    __shared__ float rs[6], rq[6];
    int b = blockIdx.x / LL, p = blockIdx.x % LL;
    int h = p / WW, w = p % WW;
    int l1 = w * HH + h;
    int d = threadIdx.x;
    size_t base = (size_t)b * KK * LL * DI;
    float y = g_y[base + ((size_t)0*LL + p)           *DI + d]
            + g_y[base + ((size_t)2*LL + (LL-1-p))    *DI + d]
            + g_y[base + ((size_t)1*LL + l1)          *DI + d]
            + g_y[base + ((size_t)3*LL + (LL-1-l1))   *DI + d];
    float s1 = y, s2 = y*y;
    #pragma unroll
    for (int o = 16; o; o >>= 1) {
        s1 += __shfl_xor_sync(0xffffffffu, s1, o);
        s2 += __shfl_xor_sync(0xffffffffu, s2, o);
    }
    int lane = d & 31, wd = d >> 5;
    if (lane == 0) { rs[wd] = s1; rq[wd] = s2; }
    __syncthreads();
    float tot = 0.f, totq = 0.f;
    #pragma unroll
    for (int i = 0; i < 6; i++) { tot += rs[i]; totq += rq[i]; }
    float mu  = tot  * (1.f/DI);
    float var = totq * (1.f/DI) - mu*mu;
    float inv = rsqrtf(var + 1e-5f);
    float yn = (y - mu) * inv * lnw[d] + lnb[d];
    yn *= g_z[((size_t)b*LL + p)*DI + d];
    sy[d] = yn;
    __syncthreads();
    int c = d % 96, half = d / 96;
    float acc = 0.f;
    const float4* wr = (const float4*)(opw + (size_t)c*DI + half*96);
    const float4* sp = (const float4*)(sy + half*96);
    #pragma unroll 6
    for (int j = 0; j < 24; j++) {
        float4 wv = wr[j];
        float4 sv = sp[j];
        acc = fmaf(wv.x, sv.x, acc);
        acc = fmaf(wv.y, sv.y, acc);
        acc = fmaf(wv.z, sv.z, acc);
        acc = fmaf(wv.w, sv.w, acc);
    }
    part[d] = acc;
    __syncthreads();
    if (d < 96) {
        size_t o = ((size_t)b*LL + p)*CC + d;
        out[o] = x[o] + part[d] + part[d + 96];
    }
}

extern "C" void kernel_launch(void* const* d_in, const int* in_sizes, int n_in,
                              void* d_out, int out_size) {
    const float* x    = (const float*)d_in[0];
    const float* ipw  = (const float*)d_in[1];
    const float* cw   = (const float*)d_in[2];
    const float* cb   = (const float*)d_in[3];
    const float* xpw  = (const float*)d_in[4];
    const float* dtw  = (const float*)d_in[5];
    const float* dtb  = (const float*)d_in[6];
    const float* alog = (const float*)d_in[7];
    const float* dsv  = (const float*)d_in[8];
    const float* lnw  = (const float*)d_in[9];
    const float* lnb  = (const float*)d_in[10];
    const float* opw  = (const float*)d_in[11];
    float* out = (float*)d_out;

    dim3 g1(BB * (LL/32), 8);
    k1_inproj<<<g1, 256>>>(x, ipw);

    k2_conv<<<BB*DI, 256>>>(cw, cb);

    k3_xproj<<<BB*KK*(LL/32), 256>>>(xpw);

    k4_delta<<<(BB*KK*DI*LL + 255)/256, 256>>>(dtw, dtb);

    dim3 gs(BB*KK*DI/4, NCH);
    k5a_pass1<<<gs, 128>>>(alog);
    k5b_combine<<<BB*KK*DI/128, 128>>>();
    k5c_pass2<<<gs, 128>>>(alog, dsv);

    k6_out<<<BB*LL, 192>>>(x, lnw, lnb, opw, out);

    (void)in_sizes; (void)n_in; (void)out_size;
}

// round 9
// speedup vs baseline: 3.2215x; 1.1691x over previous
#include <cuda_runtime.h>
#include <cstdint>

#define BB 2
#define HH 48
#define WW 48
#define CC 96
#define LL (HH*WW)        // 2304
#define DI 192
#define NS 32
#define RR 6
#define KK 4
#define NCH 6
#define CHL (LL/NCH)      // 384

// ---- scratch (device globals; no allocations allowed) ----
__device__ float  g_xraw  [BB*DI*LL];
__device__ float  g_xconv [BB*DI*LL];          // conv+silu, hw-order (b,d,l)
__device__ float  g_xconvT[BB*DI*LL];          // conv+silu, wh-order (b,d,j)
__device__ float  g_z     [BB*LL*DI];          // silu(z), (b,l,d)
__device__ float  g_dts   [BB*KK*RR*LL];       // (b,k,r,l)
__device__ float  g_BC    [BB*KK*LL*2*NS];     // (b,k,l,[B0,C0,B1,C1,...])
__device__ float  g_Bn    [BB*KK*LL*NS];       // (b,k,l,n)  B only (pass1)
__device__ float2 g_du    [BB*KK*DI*LL];       // (delta,u) per (b,k,d,l)
__device__ float  g_y     [(size_t)BB*KK*LL*DI];
__device__ float  g_hfin  [BB*KK*DI*NCH*NS];
__device__ float  g_P     [BB*KK*DI*NCH*NS];
__device__ float  g_hin   [BB*KK*DI*NCH*NS];
__device__ float  g_opwT  [DI*CC];             // transposed out_proj [d][c]

// ===== K0: transpose out_proj weight (tiny, once per launch) =====
__global__ void __launch_bounds__(256) k0_transpose(const float* __restrict__ opw) {
    int idx = blockIdx.x * 256 + threadIdx.x;
    if (idx >= DI*CC) return;
    int d = idx / CC, c = idx % CC;
    g_opwT[idx] = opw[(size_t)c*DI + d];
}

// ================= K1: in_proj + split + silu(z) =================
__global__ void __launch_bounds__(256) k1_inproj(const float* __restrict__ x,
                                                 const float* __restrict__ ipw) {
    __shared__ float sm[32][97];
    int bl = blockIdx.x;
    int lt = bl % (LL/32), b = bl / (LL/32);
    int l0 = lt * 32;
    int tid = threadIdx.x, lane = tid & 31, wid = tid >> 5;
    for (int i = tid; i < 32*96; i += 256) {
        int j = i / 96, c = i % 96;
        sm[j][c] = x[((size_t)b*LL + l0 + j)*CC + c];
    }
    __syncthreads();
    int e0 = (blockIdx.y * 8 + wid) * 6;
    float acc[6] = {0.f,0.f,0.f,0.f,0.f,0.f};
    #pragma unroll 4
    for (int c4 = 0; c4 < 24; c4++) {
        float s0 = sm[lane][c4*4+0], s1 = sm[lane][c4*4+1];
        float s2 = sm[lane][c4*4+2], s3 = sm[lane][c4*4+3];
        #pragma unroll
        for (int i = 0; i < 6; i++) {
            const float4 wv = *(const float4*)(ipw + (size_t)(e0+i)*CC + c4*4);
            acc[i] = fmaf(wv.x, s0, acc[i]);
            acc[i] = fmaf(wv.y, s1, acc[i]);
            acc[i] = fmaf(wv.z, s2, acc[i]);
            acc[i] = fmaf(wv.w, s3, acc[i]);
        }
    }
    int l = l0 + lane;
    #pragma unroll
    for (int i = 0; i < 6; i++) {
        int e = e0 + i;
        if (e < DI) {
            g_xraw[((size_t)b*DI + e)*LL + l] = acc[i];
        } else {
            float v = acc[i];
            g_z[((size_t)b*LL + l)*DI + (e - DI)] = v / (1.f + __expf(-v));
        }
    }
}

// ===== K2: depthwise conv 3x3 + bias + silu; writes hw AND wh layouts =====
__global__ void __launch_bounds__(256) k2_conv(const float* __restrict__ cw,
                                               const float* __restrict__ cb) {
    __shared__ float si[LL];
    __shared__ float so[HH*49];
    int bd = blockIdx.x;                 // = b*DI + d
    int d = bd % DI;
    int tid = threadIdx.x;
    const float* src = g_xraw + (size_t)bd * LL;
    for (int i = tid; i < LL; i += 256) si[i] = src[i];
    float wts[9];
    #pragma unroll
    for (int j = 0; j < 9; j++) wts[j] = cw[d*9 + j];
    float bias = cb[d];
    __syncthreads();
    for (int l = tid; l < LL; l += 256) {
        int h = l / WW, w = l % WW;
        float acc = bias;
        #pragma unroll
        for (int dh = -1; dh <= 1; dh++) {
            #pragma unroll
            for (int dw = -1; dw <= 1; dw++) {
                int hh = h + dh, ww2 = w + dw;
                if (hh >= 0 && hh < HH && ww2 >= 0 && ww2 < WW)
                    acc = fmaf(si[hh*WW + ww2], wts[(dh+1)*3 + (dw+1)], acc);
            }
        }
        float v = acc / (1.f + __expf(-acc));
        g_xconv[(size_t)bd*LL + l] = v;
        so[h*49 + w] = v;
    }
    __syncthreads();
    for (int j = tid; j < LL; j += 256) {     // j = w*HH + h
        int w = j / HH, h = j % HH;
        g_xconvT[(size_t)bd*LL + j] = so[h*49 + w];
    }
}

// ================= K3: x_proj -> dts / (B,C) / B-only =================
__global__ void __launch_bounds__(256) k3_xproj(const float* __restrict__ xpw) {
    __shared__ float sm[96][32];
    int blk = blockIdx.x;
    int lt = blk % (LL/32);
    int bk = blk / (LL/32);
    int k = bk % KK, b = bk / KK;
    int l0 = lt * 32;
    int tid = threadIdx.x, lane = tid & 31, wid = tid >> 5;
    const float* xbase = (k & 1) ? g_xconvT : g_xconv;
    float acc[9];
    #pragma unroll
    for (int i = 0; i < 9; i++) acc[i] = 0.f;

    for (int pass = 0; pass < 2; pass++) {
        for (int i = tid; i < 96*32; i += 256) {
            int dd = i >> 5, j = i & 31;
            int l = l0 + j;
            int idx = (k < 2) ? l : (LL - 1 - l);
            sm[dd][j] = xbase[((size_t)b*DI + pass*96 + dd)*LL + idx];
        }
        __syncthreads();
        #pragma unroll 2
        for (int dd4 = 0; dd4 < 24; dd4++) {
            float s0 = sm[dd4*4+0][lane], s1 = sm[dd4*4+1][lane];
            float s2 = sm[dd4*4+2][lane], s3 = sm[dd4*4+3][lane];
            #pragma unroll
            for (int i = 0; i < 9; i++) {
                int c = wid + 8*i;
                if (c < 70) {
                    const float4 wv = *(const float4*)(xpw + ((size_t)(k*70 + c))*DI + pass*96 + dd4*4);
                    acc[i] = fmaf(wv.x, s0, acc[i]);
                    acc[i] = fmaf(wv.y, s1, acc[i]);
                    acc[i] = fmaf(wv.z, s2, acc[i]);
                    acc[i] = fmaf(wv.w, s3, acc[i]);
                }
            }
        }
        __syncthreads();
    }
    int l = l0 + lane;
    size_t basebk = (size_t)(b*KK + k);
    #pragma unroll
    for (int i = 0; i < 9; i++) {
        int c = wid + 8*i;
        if (c < 70) {
            float v = acc[i];
            if (c < 6) {
                g_dts[(basebk*RR + c)*LL + l] = v;
            } else if (c < 38) {
                g_BC[(basebk*LL + l)*64 + 2*(c-6)] = v;
                g_Bn[(basebk*LL + l)*NS + (c-6)]   = v;
            } else {
                g_BC[(basebk*LL + l)*64 + 2*(c-38) + 1] = v;
            }
        }
    }
}

// ================= K4: dt_proj + softplus, pack (delta,u) =================
__global__ void __launch_bounds__(256) k4_delta(const float* __restrict__ dtw,
                                                const float* __restrict__ dtb) {
    int idx = blockIdx.x * 256 + threadIdx.x;
    if (idx >= BB*KK*DI*LL) return;
    int l = idx % LL;
    int d = (idx / LL) % DI;
    int k = (idx / (LL*DI)) % KK;
    int b =  idx / (LL*DI*KK);
    const float* dts = g_dts + (size_t)(b*KK + k)*RR*LL + l;
    const float* wr  = dtw + (size_t)(k*DI + d)*RR;
    float xv = dtb[k*DI + d];
    #pragma unroll
    for (int r = 0; r < RR; r++) xv = fmaf(dts[(size_t)r*LL], wr[r], xv);
    float delta = (xv > 15.f) ? xv : __logf(1.f + __expf(xv));
    const float* xbase = (k & 1) ? g_xconvT : g_xconv;
    int midx = (k < 2) ? l : (LL - 1 - l);
    float u = xbase[((size_t)b*DI + d)*LL + midx];
    g_du[idx] = make_float2(delta, u);
}

// ===== K5a: pass 1 — per-chunk local scan: h_fin, decay P (no smem/bars) ====
// grid (384, NCH-1), block 128. warp = (b,k,d), chunk = blockIdx.y.
__global__ void __launch_bounds__(128) k5a_pass1(const float* __restrict__ alog) {
    int warp = threadIdx.x >> 5;
    int lane = threadIdx.x & 31;
    int wid = blockIdx.x * 4 + warp;
    int ch  = blockIdx.y;
    int d = wid % DI;
    int k = (wid / DI) % KK;
    int b =  wid / (DI*KK);
    float a = -__expf(alog[(size_t)(k*DI + d)*NS + lane]);
    const float4* du4 = (const float4*)(g_du + (size_t)wid * LL);
    const float*  bn  = g_Bn + (size_t)(b*KK + k)*LL*NS + lane;
    float h = 0.f, S = 0.f;

    #pragma unroll 2
    for (int t = 0; t < CHL/8; t++) {
        int l0 = ch*CHL + t*8;
        float4 dub[4];
        #pragma unroll
        for (int i = 0; i < 4; i++) dub[i] = du4[(l0 >> 1) + i];
        float bv[8];
        #pragma unroll
        for (int i = 0; i < 8; i++) bv[i] = bn[(size_t)(l0 + i) * NS];
        float dl[8], ul[8], w[8];
        #pragma unroll
        for (int i = 0; i < 4; i++) {
            dl[2*i]   = dub[i].x; ul[2*i]   = dub[i].y;
            dl[2*i+1] = dub[i].z; ul[2*i+1] = dub[i].w;
        }
        #pragma unroll
        for (int i = 0; i < 8; i++) w[i] = __expf(dl[i] * a);
        #pragma unroll
        for (int i = 0; i < 8; i++) {
            h = fmaf(h, w[i], (dl[i] * ul[i]) * bv[i]);
            S += dl[i];
        }
    }
    size_t o = ((size_t)wid * NCH + ch) * NS + lane;
    g_hfin[o] = h;
    g_P[o]    = __expf(a * S);
}

// ===== K5b: combine chunk states serially (trivial) =====
__global__ void __launch_bounds__(128) k5b_combine() {
    int wid = blockIdx.x * 4 + (threadIdx.x >> 5);
    int lane = threadIdx.x & 31;
    size_t base = (size_t)wid * NCH * NS + lane;
    float hin = 0.f;
    #pragma unroll
    for (int c = 0; c < NCH; c++) {
        g_hin[base + (size_t)c*NS] = hin;
        if (c < NCH-1)
            hin = fmaf(g_P[base + (size_t)c*NS], hin, g_hfin[base + (size_t)c*NS]);
    }
}

// ===== K5c: pass 2 — full scan per chunk from h_in, y output (no smem) =====
__global__ void __launch_bounds__(128) k5c_pass2(const float* __restrict__ alog,
                                                 const float* __restrict__ dsv) {
    int warp = threadIdx.x >> 5;
    int lane = threadIdx.x & 31;
    int wid = blockIdx.x * 4 + warp;
    int ch  = blockIdx.y;
    int d = wid % DI;
    int k = (wid / DI) % KK;
    int b =  wid / (DI*KK);
    float a = -__expf(alog[(size_t)(k*DI + d)*NS + lane]);
    float dk0 = (lane == 0) ? dsv[k*DI + d] : 0.f;
    const float4* du4 = (const float4*)(g_du + (size_t)wid * LL);
    const float2* bc  = (const float2*)g_BC + (size_t)(b*KK + k)*LL*NS + lane;
    float* yo = g_y + ((size_t)(b*KK + k)*LL)*DI + d;
    float h = g_hin[((size_t)wid * NCH + ch) * NS + lane];

    #pragma unroll 2
    for (int t = 0; t < CHL/8; t++) {
        int l0 = ch*CHL + t*8;
        float4 dub[4];
        #pragma unroll
        for (int i = 0; i < 4; i++) dub[i] = du4[(l0 >> 1) + i];
        float2 bv[8];
        #pragma unroll
        for (int i = 0; i < 8; i++) bv[i] = bc[(size_t)(l0 + i) * NS];
        float dl[8], ul[8], w[8];
        #pragma unroll
        for (int i = 0; i < 4; i++) {
            dl[2*i]   = dub[i].x; ul[2*i]   = dub[i].y;
            dl[2*i+1] = dub[i].z; ul[2*i+1] = dub[i].w;
        }
        #pragma unroll
        for (int i = 0; i < 8; i++) w[i] = __expf(dl[i] * a);

        float p[8];
        #pragma unroll
        for (int i = 0; i < 8; i++) {
            h = fmaf(h, w[i], (dl[i] * ul[i]) * bv[i].x);
            p[i] = fmaf(dk0, ul[i], h * bv[i].y);
        }

        // value-halving multi-reduction: 9 shfls for 8 sums
        {
            bool hi = (lane & 16) != 0;
            #pragma unroll
            for (int i = 0; i < 4; i++) {
                float send = hi ? p[i] : p[i+4];
                float keep = hi ? p[i+4] : p[i];
                p[i] = keep + __shfl_xor_sync(0xffffffffu, send, 16);
            }
        }
        {
            bool hi = (lane & 8) != 0;
            #pragma unroll
            for (int i = 0; i < 2; i++) {
                float send = hi ? p[i] : p[i+2];
                float keep = hi ? p[i+2] : p[i];
                p[i] = keep + __shfl_xor_sync(0xffffffffu, send, 8);
            }
        }
        {
            bool hi = (lane & 4) != 0;
            float send = hi ? p[0] : p[1];
            float keep = hi ? p[1] : p[0];
            p[0] = keep + __shfl_xor_sync(0xffffffffu, send, 4);
        }
        p[0] += __shfl_xor_sync(0xffffffffu, p[0], 2);
        p[0] += __shfl_xor_sync(0xffffffffu, p[0], 1);
        if ((lane & 3) == 0) yo[(size_t)(l0 + (lane >> 2)) * DI] = p[0];
    }
}

// ================= K6: combine dirs + LN + gate + out_proj + residual =====
__global__ void __launch_bounds__(192) k6_out(const float* __restrict__ x,
                                              const float* __restrict__ lnw,
                                              const float* __restrict__ lnb,
                                              float* __restrict__ out) {
    __shared__ float sy[DI];
    __shared__ float part8[8][CC];
    __shared__ float rs[6], rq[6];
    int b = blockIdx.x / LL, p = blockIdx.x % LL;
    int h = p / WW, w = p % WW;
    int l1 = w * HH + h;
    int d = threadIdx.x;
    size_t base = (size_t)b * KK * LL * DI;
    float y = g_y[base + ((size_t)0*LL + p)           *DI + d]
            + g_y[base + ((size_t)2*LL + (LL-1-p))    *DI + d]
            + g_y[base + ((size_t)1*LL + l1)          *DI + d]
            + g_y[base + ((size_t)3*LL + (LL-1-l1))   *DI + d];
    float s1 = y, s2 = y*y;
    #pragma unroll
    for (int o = 16; o; o >>= 1) {
        s1 += __shfl_xor_sync(0xffffffffu, s1, o);
        s2 += __shfl_xor_sync(0xffffffffu, s2, o);
    }
    int lane = d & 31, wd = d >> 5;
    if (lane == 0) { rs[wd] = s1; rq[wd] = s2; }
    __syncthreads();
    float tot = 0.f, totq = 0.f;
    #pragma unroll
    for (int i = 0; i < 6; i++) { tot += rs[i]; totq += rq[i]; }
    float mu  = tot  * (1.f/DI);
    float var = totq * (1.f/DI) - mu*mu;
    float inv = rsqrtf(var + 1e-5f);
    float yn = (y - mu) * inv * lnw[d] + lnb[d];
    yn *= g_z[((size_t)b*LL + p)*DI + d];
    sy[d] = yn;
    __syncthreads();

    // GEMM: thread (q,m): q = 24-row d-slice, m = float4 column group
    int q = d / 24, m = d % 24;
    const float4* wt = (const float4*)g_opwT + (size_t)q*24*24 + m;
    float4 acc = make_float4(0.f, 0.f, 0.f, 0.f);
    #pragma unroll 6
    for (int j = 0; j < 24; j++) {
        float sv = sy[q*24 + j];
        float4 wv = wt[(size_t)j*24];
        acc.x = fmaf(wv.x, sv, acc.x);
        acc.y = fmaf(wv.y, sv, acc.y);
        acc.z = fmaf(wv.z, sv, acc.z);
        acc.w = fmaf(wv.w, sv, acc.w);
    }
    *(float4*)&part8[q][4*m] = acc;
    __syncthreads();
    if (d < CC) {
        float s = 0.f;
        #pragma unroll
        for (int i = 0; i < 8; i++) s += part8[i][d];
        size_t o = ((size_t)b*LL + p)*CC + d;
        out[o] = x[o] + s;
    }
}

extern "C" void kernel_launch(void* const* d_in, const int* in_sizes, int n_in,
                              void* d_out, int out_size) {
    const float* x    = (const float*)d_in[0];
    const float* ipw  = (const float*)d_in[1];
    const float* cw   = (const float*)d_in[2];
    const float* cb   = (const float*)d_in[3];
    const float* xpw  = (const float*)d_in[4];
    const float* dtw  = (const float*)d_in[5];
    const float* dtb  = (const float*)d_in[6];
    const float* alog = (const float*)d_in[7];
    const float* dsv  = (const float*)d_in[8];
    const float* lnw  = (const float*)d_in[9];
    const float* lnb  = (const float*)d_in[10];
    const float* opw  = (const float*)d_in[11];
    float* out = (float*)d_out;

    k0_transpose<<<(DI*CC + 255)/256, 256>>>(opw);

    dim3 g1(BB * (LL/32), 8);
    k1_inproj<<<g1, 256>>>(x, ipw);

    k2_conv<<<BB*DI, 256>>>(cw, cb);

    k3_xproj<<<BB*KK*(LL/32), 256>>>(xpw);

    k4_delta<<<(BB*KK*DI*LL + 255)/256, 256>>>(dtw, dtb);

    dim3 gs1(BB*KK*DI/4, NCH-1);
    k5a_pass1<<<gs1, 128>>>(alog);
    k5b_combine<<<BB*KK*DI/128, 128>>>();
    dim3 gs2(BB*KK*DI/4, NCH);
    k5c_pass2<<<gs2, 128>>>(alog, dsv);

    k6_out<<<BB*LL, 192>>>(x, lnw, lnb, out);

    (void)in_sizes; (void)n_in; (void)out_size;
}

// round 10
// speedup vs baseline: 3.4016x; 1.0559x over previous
#include <cuda_runtime.h>
#include <cstdint>

#define BB 2
#define HH 48
#define WW 48
#define CC 96
#define LL (HH*WW)        // 2304
#define DI 192
#define NS 32
#define RR 6
#define KK 4
#define NCH 6
#define CHL (LL/NCH)      // 384

// ---- scratch (device globals; no allocations allowed) ----
__device__ float  g_xraw  [BB*DI*LL];
__device__ float  g_xconv [BB*DI*LL];          // conv+silu, hw-order (b,d,l)
__device__ float  g_xconvT[BB*DI*LL];          // conv+silu, wh-order (b,d,j)
__device__ float  g_z     [BB*LL*DI];          // silu(z), (b,l,d)
__device__ float  g_dts   [BB*KK*RR*LL];       // (b,k,r,l)
__device__ float  g_BC    [BB*KK*LL*2*NS];     // (b,k,l,[B0,C0,B1,C1,...])
__device__ float  g_Bn    [BB*KK*LL*NS];       // (b,k,l,n)  B only (pass1)
__device__ float2 g_du    [BB*KK*DI*LL];       // (delta,u) per (b,k,d,l)
__device__ float  g_y     [(size_t)BB*KK*LL*DI];
__device__ float  g_hfin  [BB*KK*DI*NCH*NS];
__device__ float  g_P     [BB*KK*DI*NCH*NS];
__device__ float  g_hin   [BB*KK*DI*NCH*NS];
__device__ float  g_opwT  [DI*CC];             // transposed out_proj [d][c]

// ===== K0: transpose out_proj weight (tiny, once per launch) =====
__global__ void __launch_bounds__(256) k0_transpose(const float* __restrict__ opw) {
    int idx = blockIdx.x * 256 + threadIdx.x;
    if (idx >= DI*CC) return;
    int d = idx / CC, c = idx % CC;
    g_opwT[idx] = opw[(size_t)c*DI + d];
}

// ================= K1: in_proj + split + silu(z) =================
// __launch_bounds__(256,4): cap regs at 64 so 4 CTAs/SM fit (single-wave occupancy)
__global__ void __launch_bounds__(256, 4) k1_inproj(const float* __restrict__ x,
                                                    const float* __restrict__ ipw) {
    __shared__ float sm[32][97];
    int bl = blockIdx.x;
    int lt = bl % (LL/32), b = bl / (LL/32);
    int l0 = lt * 32;
    int tid = threadIdx.x, lane = tid & 31, wid = tid >> 5;
    for (int i = tid; i < 32*96; i += 256) {
        int j = i / 96, c = i % 96;
        sm[j][c] = x[((size_t)b*LL + l0 + j)*CC + c];
    }
    __syncthreads();
    int e0 = (blockIdx.y * 8 + wid) * 6;
    float acc[6] = {0.f,0.f,0.f,0.f,0.f,0.f};
    #pragma unroll 4
    for (int c4 = 0; c4 < 24; c4++) {
        float s0 = sm[lane][c4*4+0], s1 = sm[lane][c4*4+1];
        float s2 = sm[lane][c4*4+2], s3 = sm[lane][c4*4+3];
        #pragma unroll
        for (int i = 0; i < 6; i++) {
            const float4 wv = *(const float4*)(ipw + (size_t)(e0+i)*CC + c4*4);
            acc[i] = fmaf(wv.x, s0, acc[i]);
            acc[i] = fmaf(wv.y, s1, acc[i]);
            acc[i] = fmaf(wv.z, s2, acc[i]);
            acc[i] = fmaf(wv.w, s3, acc[i]);
        }
    }
    int l = l0 + lane;
    #pragma unroll
    for (int i = 0; i < 6; i++) {
        int e = e0 + i;
        if (e < DI) {
            g_xraw[((size_t)b*DI + e)*LL + l] = acc[i];
        } else {
            float v = acc[i];
            g_z[((size_t)b*LL + l)*DI + (e - DI)] = v / (1.f + __expf(-v));
        }
    }
}

// ===== K2: depthwise conv 3x3 + bias + silu; writes hw AND wh layouts =====
__global__ void __launch_bounds__(256) k2_conv(const float* __restrict__ cw,
                                               const float* __restrict__ cb) {
    __shared__ float si[LL];
    __shared__ float so[HH*49];
    int bd = blockIdx.x;                 // = b*DI + d
    int d = bd % DI;
    int tid = threadIdx.x;
    const float* src = g_xraw + (size_t)bd * LL;
    for (int i = tid; i < LL; i += 256) si[i] = src[i];
    float wts[9];
    #pragma unroll
    for (int j = 0; j < 9; j++) wts[j] = cw[d*9 + j];
    float bias = cb[d];
    __syncthreads();
    for (int l = tid; l < LL; l += 256) {
        int h = l / WW, w = l % WW;
        float acc = bias;
        #pragma unroll
        for (int dh = -1; dh <= 1; dh++) {
            #pragma unroll
            for (int dw = -1; dw <= 1; dw++) {
                int hh = h + dh, ww2 = w + dw;
                if (hh >= 0 && hh < HH && ww2 >= 0 && ww2 < WW)
                    acc = fmaf(si[hh*WW + ww2], wts[(dh+1)*3 + (dw+1)], acc);
            }
        }
        float v = acc / (1.f + __expf(-acc));
        g_xconv[(size_t)bd*LL + l] = v;
        so[h*49 + w] = v;
    }
    __syncthreads();
    for (int j = tid; j < LL; j += 256) {     // j = w*HH + h
        int w = j / HH, h = j % HH;
        g_xconvT[(size_t)bd*LL + j] = so[h*49 + w];
    }
}

// ================= K3: x_proj -> dts / (B,C) / B-only =================
// __launch_bounds__(256,4): regs<=64 so 576 CTAs run as ONE wave of 4/SM.
__global__ void __launch_bounds__(256, 4) k3_xproj(const float* __restrict__ xpw) {
    __shared__ float sm[96][32];
    int blk = blockIdx.x;
    int lt = blk % (LL/32);
    int bk = blk / (LL/32);
    int k = bk % KK, b = bk / KK;
    int l0 = lt * 32;
    int tid = threadIdx.x, lane = tid & 31, wid = tid >> 5;
    const float* xbase = (k & 1) ? g_xconvT : g_xconv;
    float acc[9];
    #pragma unroll
    for (int i = 0; i < 9; i++) acc[i] = 0.f;

    for (int pass = 0; pass < 2; pass++) {
        for (int i = tid; i < 96*32; i += 256) {
            int dd = i >> 5, j = i & 31;
            int l = l0 + j;
            int idx = (k < 2) ? l : (LL - 1 - l);
            sm[dd][j] = xbase[((size_t)b*DI + pass*96 + dd)*LL + idx];
        }
        __syncthreads();
        #pragma unroll 2
        for (int dd4 = 0; dd4 < 24; dd4++) {
            float s0 = sm[dd4*4+0][lane], s1 = sm[dd4*4+1][lane];
            float s2 = sm[dd4*4+2][lane], s3 = sm[dd4*4+3][lane];
            #pragma unroll
            for (int i = 0; i < 9; i++) {
                int c = wid + 8*i;
                if (c < 70) {
                    const float4 wv = *(const float4*)(xpw + ((size_t)(k*70 + c))*DI + pass*96 + dd4*4);
                    acc[i] = fmaf(wv.x, s0, acc[i]);
                    acc[i] = fmaf(wv.y, s1, acc[i]);
                    acc[i] = fmaf(wv.z, s2, acc[i]);
                    acc[i] = fmaf(wv.w, s3, acc[i]);
                }
            }
        }
        __syncthreads();
    }
    int l = l0 + lane;
    size_t basebk = (size_t)(b*KK + k);
    #pragma unroll
    for (int i = 0; i < 9; i++) {
        int c = wid + 8*i;
        if (c < 70) {
            float v = acc[i];
            if (c < 6) {
                g_dts[(basebk*RR + c)*LL + l] = v;
            } else if (c < 38) {
                g_BC[(basebk*LL + l)*64 + 2*(c-6)] = v;
                g_Bn[(basebk*LL + l)*NS + (c-6)]   = v;
            } else {
                g_BC[(basebk*LL + l)*64 + 2*(c-38) + 1] = v;
            }
        }
    }
}

// ================= K4: dt_proj + softplus, pack (delta,u) =================
__global__ void __launch_bounds__(256) k4_delta(const float* __restrict__ dtw,
                                                const float* __restrict__ dtb) {
    int idx = blockIdx.x * 256 + threadIdx.x;
    if (idx >= BB*KK*DI*LL) return;
    int l = idx % LL;
    int d = (idx / LL) % DI;
    int k = (idx / (LL*DI)) % KK;
    int b =  idx / (LL*DI*KK);
    const float* dts = g_dts + (size_t)(b*KK + k)*RR*LL + l;
    const float* wr  = dtw + (size_t)(k*DI + d)*RR;
    float xv = dtb[k*DI + d];
    #pragma unroll
    for (int r = 0; r < RR; r++) xv = fmaf(dts[(size_t)r*LL], wr[r], xv);
    float delta = (xv > 15.f) ? xv : __logf(1.f + __expf(xv));
    const float* xbase = (k & 1) ? g_xconvT : g_xconv;
    int midx = (k < 2) ? l : (LL - 1 - l);
    float u = xbase[((size_t)b*DI + d)*LL + midx];
    g_du[idx] = make_float2(delta, u);
}

// ===== K5a: pass 1 — per-chunk local scan: h_fin, decay P (no smem/bars) ====
__global__ void __launch_bounds__(128) k5a_pass1(const float* __restrict__ alog) {
    int warp = threadIdx.x >> 5;
    int lane = threadIdx.x & 31;
    int wid = blockIdx.x * 4 + warp;
    int ch  = blockIdx.y;
    int d = wid % DI;
    int k = (wid / DI) % KK;
    int b =  wid / (DI*KK);
    float a = -__expf(alog[(size_t)(k*DI + d)*NS + lane]);
    const float4* du4 = (const float4*)(g_du + (size_t)wid * LL);
    const float*  bn  = g_Bn + (size_t)(b*KK + k)*LL*NS + lane;
    float h = 0.f, S = 0.f;

    #pragma unroll 2
    for (int t = 0; t < CHL/8; t++) {
        int l0 = ch*CHL + t*8;
        float4 dub[4];
        #pragma unroll
        for (int i = 0; i < 4; i++) dub[i] = du4[(l0 >> 1) + i];
        float bv[8];
        #pragma unroll
        for (int i = 0; i < 8; i++) bv[i] = bn[(size_t)(l0 + i) * NS];
        float dl[8], ul[8], w[8];
        #pragma unroll
        for (int i = 0; i < 4; i++) {
            dl[2*i]   = dub[i].x; ul[2*i]   = dub[i].y;
            dl[2*i+1] = dub[i].z; ul[2*i+1] = dub[i].w;
        }
        #pragma unroll
        for (int i = 0; i < 8; i++) w[i] = __expf(dl[i] * a);
        #pragma unroll
        for (int i = 0; i < 8; i++) {
            h = fmaf(h, w[i], (dl[i] * ul[i]) * bv[i]);
            S += dl[i];
        }
    }
    size_t o = ((size_t)wid * NCH + ch) * NS + lane;
    g_hfin[o] = h;
    g_P[o]    = __expf(a * S);
}

// ===== K5b: combine chunk states serially (trivial) =====
__global__ void __launch_bounds__(128) k5b_combine() {
    int wid = blockIdx.x * 4 + (threadIdx.x >> 5);
    int lane = threadIdx.x & 31;
    size_t base = (size_t)wid * NCH * NS + lane;
    float hin = 0.f;
    #pragma unroll
    for (int c = 0; c < NCH; c++) {
        g_hin[base + (size_t)c*NS] = hin;
        if (c < NCH-1)
            hin = fmaf(g_P[base + (size_t)c*NS], hin, g_hfin[base + (size_t)c*NS]);
    }
}

// ===== K5c: pass 2 — full scan per chunk from h_in, y output (no smem) =====
__global__ void __launch_bounds__(128) k5c_pass2(const float* __restrict__ alog,
                                                 const float* __restrict__ dsv) {
    int warp = threadIdx.x >> 5;
    int lane = threadIdx.x & 31;
    int wid = blockIdx.x * 4 + warp;
    int ch  = blockIdx.y;
    int d = wid % DI;
    int k = (wid / DI) % KK;
    int b =  wid / (DI*KK);
    float a = -__expf(alog[(size_t)(k*DI + d)*NS + lane]);
    float dk0 = (lane == 0) ? dsv[k*DI + d] : 0.f;
    const float4* du4 = (const float4*)(g_du + (size_t)wid * LL);
    const float2* bc  = (const float2*)g_BC + (size_t)(b*KK + k)*LL*NS + lane;
    float* yo = g_y + ((size_t)(b*KK + k)*LL)*DI + d;
    float h = g_hin[((size_t)wid * NCH + ch) * NS + lane];

    #pragma unroll 2
    for (int t = 0; t < CHL/8; t++) {
        int l0 = ch*CHL + t*8;
        float4 dub[4];
        #pragma unroll
        for (int i = 0; i < 4; i++) dub[i] = du4[(l0 >> 1) + i];
        float2 bv[8];
        #pragma unroll
        for (int i = 0; i < 8; i++) bv[i] = bc[(size_t)(l0 + i) * NS];
        float dl[8], ul[8], w[8];
        #pragma unroll
        for (int i = 0; i < 4; i++) {
            dl[2*i]   = dub[i].x; ul[2*i]   = dub[i].y;
            dl[2*i+1] = dub[i].z; ul[2*i+1] = dub[i].w;
        }
        #pragma unroll
        for (int i = 0; i < 8; i++) w[i] = __expf(dl[i] * a);

        float p[8];
        #pragma unroll
        for (int i = 0; i < 8; i++) {
            h = fmaf(h, w[i], (dl[i] * ul[i]) * bv[i].x);
            p[i] = fmaf(dk0, ul[i], h * bv[i].y);
        }

        // value-halving multi-reduction: 9 shfls for 8 sums
        {
            bool hi = (lane & 16) != 0;
            #pragma unroll
            for (int i = 0; i < 4; i++) {
                float send = hi ? p[i] : p[i+4];
                float keep = hi ? p[i+4] : p[i];
                p[i] = keep + __shfl_xor_sync(0xffffffffu, send, 16);
            }
        }
        {
            bool hi = (lane & 8) != 0;
            #pragma unroll
            for (int i = 0; i < 2; i++) {
                float send = hi ? p[i] : p[i+2];
                float keep = hi ? p[i+2] : p[i];
                p[i] = keep + __shfl_xor_sync(0xffffffffu, send, 8);
            }
        }
        {
            bool hi = (lane & 4) != 0;
            float send = hi ? p[0] : p[1];
            float keep = hi ? p[1] : p[0];
            p[0] = keep + __shfl_xor_sync(0xffffffffu, send, 4);
        }
        p[0] += __shfl_xor_sync(0xffffffffu, p[0], 2);
        p[0] += __shfl_xor_sync(0xffffffffu, p[0], 1);
        if ((lane & 3) == 0) yo[(size_t)(l0 + (lane >> 2)) * DI] = p[0];
    }
}

// ================= K6: combine dirs + LN + gate + out_proj + residual =====
__global__ void __launch_bounds__(192) k6_out(const float* __restrict__ x,
                                              const float* __restrict__ lnw,
                                              const float* __restrict__ lnb,
                                              float* __restrict__ out) {
    __shared__ float sy[DI];
    __shared__ float part8[8][CC];
    __shared__ float rs[6], rq[6];
    int b = blockIdx.x / LL, p = blockIdx.x % LL;
    int h = p / WW, w = p % WW;
    int l1 = w * HH + h;
    int d = threadIdx.x;
    size_t base = (size_t)b * KK * LL * DI;
    float y = g_y[base + ((size_t)0*LL + p)           *DI + d]
            + g_y[base + ((size_t)2*LL + (LL-1-p))    *DI + d]
            + g_y[base + ((size_t)1*LL + l1)          *DI + d]
            + g_y[base + ((size_t)3*LL + (LL-1-l1))   *DI + d];
    float s1 = y, s2 = y*y;
    #pragma unroll
    for (int o = 16; o; o >>= 1) {
        s1 += __shfl_xor_sync(0xffffffffu, s1, o);
        s2 += __shfl_xor_sync(0xffffffffu, s2, o);
    }
    int lane = d & 31, wd = d >> 5;
    if (lane == 0) { rs[wd] = s1; rq[wd] = s2; }
    __syncthreads();
    float tot = 0.f, totq = 0.f;
    #pragma unroll
    for (int i = 0; i < 6; i++) { tot += rs[i]; totq += rq[i]; }
    float mu  = tot  * (1.f/DI);
    float var = totq * (1.f/DI) - mu*mu;
    float inv = rsqrtf(var + 1e-5f);
    float yn = (y - mu) * inv * lnw[d] + lnb[d];
    yn *= g_z[((size_t)b*LL + p)*DI + d];
    sy[d] = yn;
    __syncthreads();

    // GEMM: thread (q,m): q = 24-row d-slice, m = float4 column group
    int q = d / 24, m = d % 24;
    const float4* wt = (const float4*)g_opwT + (size_t)q*24*24 + m;
    float4 acc = make_float4(0.f, 0.f, 0.f, 0.f);
    #pragma unroll 6
    for (int j = 0; j < 24; j++) {
        float sv = sy[q*24 + j];
        float4 wv = wt[(size_t)j*24];
        acc.x = fmaf(wv.x, sv, acc.x);
        acc.y = fmaf(wv.y, sv, acc.y);
        acc.z = fmaf(wv.z, sv, acc.z);
        acc.w = fmaf(wv.w, sv, acc.w);
    }
    *(float4*)&part8[q][4*m] = acc;
    __syncthreads();
    if (d < CC) {
        float s = 0.f;
        #pragma unroll
        for (int i = 0; i < 8; i++) s += part8[i][d];
        size_t o = ((size_t)b*LL + p)*CC + d;
        out[o] = x[o] + s;
    }
}

extern "C" void kernel_launch(void* const* d_in, const int* in_sizes, int n_in,
                              void* d_out, int out_size) {
    const float* x    = (const float*)d_in[0];
    const float* ipw  = (const float*)d_in[1];
    const float* cw   = (const float*)d_in[2];
    const float* cb   = (const float*)d_in[3];
    const float* xpw  = (const float*)d_in[4];
    const float* dtw  = (const float*)d_in[5];
    const float* dtb  = (const float*)d_in[6];
    const float* alog = (const float*)d_in[7];
    const float* dsv  = (const float*)d_in[8];
    const float* lnw  = (const float*)d_in[9];
    const float* lnb  = (const float*)d_in[10];
    const float* opw  = (const float*)d_in[11];
    float* out = (float*)d_out;

    k0_transpose<<<(DI*CC + 255)/256, 256>>>(opw);

    dim3 g1(BB * (LL/32), 8);
    k1_inproj<<<g1, 256>>>(x, ipw);

    k2_conv<<<BB*DI, 256>>>(cw, cb);

    k3_xproj<<<BB*KK*(LL/32), 256>>>(xpw);

    k4_delta<<<(BB*KK*DI*LL + 255)/256, 256>>>(dtw, dtb);

    dim3 gs1(BB*KK*DI/4, NCH-1);
    k5a_pass1<<<gs1, 128>>>(alog);
    k5b_combine<<<BB*KK*DI/128, 128>>>();
    dim3 gs2(BB*KK*DI/4, NCH);
    k5c_pass2<<<gs2, 128>>>(alog, dsv);

    k6_out<<<BB*LL, 192>>>(x, lnw, lnb, out);

    (void)in_sizes; (void)n_in; (void)out_size;
}